// round 3
// baseline (speedup 1.0000x reference)
#include <cuda_runtime.h>
#include <math.h>

#define B_  2048
#define D_  64
#define H_  512
#define BT  16     // samples per block
#define NT  512    // threads per block

typedef unsigned long long ull;

// Precomputed E[j][k] = W2[j,k] * sum_{m<64} W1[m,j] * W3[k,m]
__device__ float g_E[H_ * H_];

// ---------------- f32x2 packed helpers (sm_100+) ----------------
__device__ __forceinline__ ull pk2(float lo, float hi) {
    ull d;
    asm("mov.b64 %0, {%1, %2};" : "=l"(d)
        : "r"(__float_as_uint(lo)), "r"(__float_as_uint(hi)));
    return d;
}
__device__ __forceinline__ ull dup2(float v) { return pk2(v, v); }
__device__ __forceinline__ ull f2fma(ull a, ull b, ull c) {
    ull d;
    asm("fma.rn.f32x2 %0, %1, %2, %3;" : "=l"(d) : "l"(a), "l"(b), "l"(c));
    return d;
}
__device__ __forceinline__ ull f2add(ull a, ull b) {
    ull d;
    asm("add.rn.f32x2 %0, %1, %2;" : "=l"(d) : "l"(a), "l"(b));
    return d;
}
__device__ __forceinline__ void upk(ull v, float& lo, float& hi) {
    unsigned ulo, uhi;
    asm("mov.b64 {%0, %1}, %2;" : "=r"(ulo), "=r"(uhi) : "l"(v));
    lo = __uint_as_float(ulo); hi = __uint_as_float(uhi);
}

// ---------------------------------------------------------------------------
// Kernel 0: build E. grid = H_ (j), block = H_ (k). 16.8M MACs — negligible.
// ---------------------------------------------------------------------------
__global__ __launch_bounds__(H_) void compute_E_kernel(
    const float* __restrict__ W1,   // (65, 512)
    const float* __restrict__ W2,   // (512, 512)
    const float* __restrict__ W3)   // (512, 64)
{
    __shared__ float w1col[D_];
    const int j = blockIdx.x;
    const int k = threadIdx.x;
    if (k < D_) w1col[k] = W1[k * H_ + j];
    __syncthreads();

    float r[D_];
    const float4* w3r = (const float4*)(W3 + k * D_);
#pragma unroll
    for (int q = 0; q < D_ / 4; q++) {
        float4 v = w3r[q];
        r[4*q+0] = v.x; r[4*q+1] = v.y; r[4*q+2] = v.z; r[4*q+3] = v.w;
    }
    float acc = 0.f;
#pragma unroll
    for (int m = 0; m < D_; m++) acc = fmaf(w1col[m], r[m], acc);

    g_E[j * H_ + k] = W2[j * H_ + k] * acc;
}

// ---------------------------------------------------------------------------
// Main kernel, 16 samples/block, 512 threads, f32x2-packed over sample pairs.
// Dynamic smem layout (u64 units):
//   h0  [65][8]    input pairs                        520 u64
//   hb  [512][10]  h1 pairs (8 used, stride-10 pad)  5120
//   tb  [512][10]  (h1^2 - 1) pairs                  5120
//   h2b [512][10]  h2 pairs                          5120
//   dvsh[16][2]    per-warp div partials               32
// ---------------------------------------------------------------------------
__global__ __launch_bounds__(NT, 1) void cnf_main_kernel(
    const float* __restrict__ t,  const float* __restrict__ x,
    const float* __restrict__ W1, const float* __restrict__ b1,
    const float* __restrict__ W2, const float* __restrict__ b2,
    const float* __restrict__ W3, const float* __restrict__ b3,
    float* __restrict__ out)
{
    extern __shared__ ull sm[];
    ull* h0   = sm;                 // 520
    ull* hb   = h0 + 65 * 8;        // 5120
    ull* tb   = hb + 512 * 10;      // 5120
    ull* h2b  = tb + 512 * 10;      // 5120
    ull* dvsh = h2b + 512 * 10;     // 32

    const int tid = threadIdx.x;
    const int s0  = blockIdx.x * BT;

    // ---- load x tile (+t), layout [i][s] so sample pairs are contiguous ----
    float* h0f = (float*)h0;
    for (int idx = tid; idx < BT * (D_ + 1); idx += NT) {
        int s = idx / (D_ + 1);
        int i = idx - s * (D_ + 1);
        float v = (i < D_) ? x[(size_t)(s0 + s) * (D_ + 1) + i] : t[0];
        h0f[i * BT + s] = v;
    }
    __syncthreads();

    // ---- Phase 1: h1 = tanh(x @ W1 + b1); also t1 = h1^2 - 1 ----
    {
        const int j = tid;
        ull acc[8];
#pragma unroll
        for (int p = 0; p < 8; p++) acc[p] = 0ull;

#pragma unroll 5
        for (int i = 0; i < D_ + 1; i++) {
            ull wd = dup2(W1[i * H_ + j]);
            const ulonglong2* hp = (const ulonglong2*)(h0 + i * 8);
#pragma unroll
            for (int c = 0; c < 4; c++) {
                ulonglong2 hv = hp[c];
                acc[2*c]   = f2fma(hv.x, wd, acc[2*c]);
                acc[2*c+1] = f2fma(hv.y, wd, acc[2*c+1]);
            }
        }
        float b = b1[j];
#pragma unroll
        for (int p = 0; p < 8; p++) {
            float zl, zh; upk(acc[p], zl, zh);
            float hl = tanhf(zl + b), hh = tanhf(zh + b);
            hb[j * 10 + p] = pk2(hl, hh);
            tb[j * 10 + p] = pk2(fmaf(hl, hl, -1.f), fmaf(hh, hh, -1.f));
        }
    }
    __syncthreads();

    // ---- Phase 2: z = h1@W2, a' = t1@E, fused; h2 = tanh(z+b2);
    //      div' += a' * (h2^2-1)   (signs cancel: a*v == a'*v')
    const int q  = tid >> 7;      // sample-quarter: pairs 2q, 2q+1
    const int kt = tid & 127;
    const int k0 = kt * 4;        // this thread owns k0..k0+3

    ull z2[2][4], a2[2][4];
#pragma unroll
    for (int pi = 0; pi < 2; pi++)
#pragma unroll
        for (int c = 0; c < 4; c++) { z2[pi][c] = 0ull; a2[pi][c] = 0ull; }

#pragma unroll 2
    for (int j = 0; j < H_; j++) {
        float4 w4 = *(const float4*)(W2  + (size_t)j * H_ + k0);
        float4 e4 = *(const float4*)(g_E + (size_t)j * H_ + k0);
        ulonglong2 hp = *(const ulonglong2*)(hb + j * 10 + 2 * q);
        ulonglong2 tp = *(const ulonglong2*)(tb + j * 10 + 2 * q);
        ull wd[4] = {dup2(w4.x), dup2(w4.y), dup2(w4.z), dup2(w4.w)};
        ull ed[4] = {dup2(e4.x), dup2(e4.y), dup2(e4.z), dup2(e4.w)};
#pragma unroll
        for (int c = 0; c < 4; c++) {
            z2[0][c] = f2fma(hp.x, wd[c], z2[0][c]);
            z2[1][c] = f2fma(hp.y, wd[c], z2[1][c]);
            a2[0][c] = f2fma(tp.x, ed[c], a2[0][c]);
            a2[1][c] = f2fma(tp.y, ed[c], a2[1][c]);
        }
    }

    // epilogue: tanh, v' = h2^2-1, divergence partials, stash h2
    {
        const ull NEG1 = dup2(-1.f);
        float4 b4 = *(const float4*)(b2 + k0);
        float bv[4] = {b4.x, b4.y, b4.z, b4.w};
        ull dv[2] = {0ull, 0ull};
#pragma unroll
        for (int c = 0; c < 4; c++) {
#pragma unroll
            for (int pi = 0; pi < 2; pi++) {
                float zl, zh; upk(z2[pi][c], zl, zh);
                float hl = tanhf(zl + bv[c]), hh = tanhf(zh + bv[c]);
                ull hp = pk2(hl, hh);
                ull v2 = f2fma(hp, hp, NEG1);          // h2^2 - 1
                dv[pi] = f2fma(a2[pi][c], v2, dv[pi]);
                h2b[(k0 + c) * 10 + 2 * q + pi] = hp;
            }
        }
        // warp-reduce over the 32 kt-lanes (each covers distinct k)
#pragma unroll
        for (int off = 16; off; off >>= 1) {
            dv[0] = f2add(dv[0], __shfl_xor_sync(0xffffffffu, dv[0], off));
            dv[1] = f2add(dv[1], __shfl_xor_sync(0xffffffffu, dv[1], off));
        }
        if ((tid & 31) == 0) {
            int w = tid >> 5;
            dvsh[w * 2 + 0] = dv[0];
            dvsh[w * 2 + 1] = dv[1];
        }
    }
    __syncthreads();

    // ---- Phase 3: out = (h2 @ W3 + b3)/2, plus div column ----
    {
        const int p = tid >> 6;    // sample pair 0..7
        const int m = tid & 63;    // output column
        ull o2 = 0ull;
#pragma unroll 4
        for (int k = 0; k < H_; k++) {
            ull hp = h2b[k * 10 + p];
            o2 = f2fma(hp, dup2(W3[k * D_ + m]), o2);
        }
        float ol, oh; upk(o2, ol, oh);
        float bm = b3[m];
        out[(size_t)(s0 + 2*p    ) * (D_ + 1) + m] = 0.5f * (ol + bm);
        out[(size_t)(s0 + 2*p + 1) * (D_ + 1) + m] = 0.5f * (oh + bm);
    }
    if (tid < BT) {
        int s  = tid;
        int qq = s >> 2, pi = (s >> 1) & 1, hl = s & 1;
        float d = 0.f;
#pragma unroll
        for (int w = qq * 4; w < qq * 4 + 4; w++) {
            float lo, hi; upk(dvsh[w * 2 + pi], lo, hi);
            d += hl ? hi : lo;
        }
        out[(size_t)(s0 + s) * (D_ + 1) + D_] = 0.5f * d;
    }
}

#define SMEM_BYTES ((65*8 + 3*512*10 + 32) * 8)

extern "C" void kernel_launch(void* const* d_in, const int* in_sizes, int n_in,
                              void* d_out, int out_size) {
    const float* t  = (const float*)d_in[0];
    const float* x  = (const float*)d_in[1];
    const float* W1 = (const float*)d_in[2];
    const float* b1 = (const float*)d_in[3];
    const float* W2 = (const float*)d_in[4];
    const float* b2 = (const float*)d_in[5];
    const float* W3 = (const float*)d_in[6];
    const float* b3 = (const float*)d_in[7];
    float* out = (float*)d_out;

    cudaFuncSetAttribute(cnf_main_kernel,
                         cudaFuncAttributeMaxDynamicSharedMemorySize, SMEM_BYTES);

    compute_E_kernel<<<H_, H_>>>(W1, W2, W3);
    cnf_main_kernel<<<B_ / BT, NT, SMEM_BYTES>>>(t, x, W1, b1, W2, b2, W3, b3, out);
}

// round 4
// speedup vs baseline: 1.2794x; 1.2794x over previous
#include <cuda_runtime.h>
#include <math.h>

#define B_  2048
#define D_  64
#define H_  512
#define BT  16     // samples per block
#define NT  512    // threads per block

typedef unsigned long long ull;

// Precomputed E[j][k] = W2[j,k] * sum_{m<64} W1[m,j] * W3[k,m]
__device__ float g_E[H_ * H_];

// ---------------- f32x2 packed helpers (sm_100+) ----------------
__device__ __forceinline__ ull pk2(float lo, float hi) {
    ull d;
    asm("mov.b64 %0, {%1, %2};" : "=l"(d)
        : "r"(__float_as_uint(lo)), "r"(__float_as_uint(hi)));
    return d;
}
__device__ __forceinline__ ull dup2(float v) { return pk2(v, v); }
__device__ __forceinline__ ull f2fma(ull a, ull b, ull c) {
    ull d;
    asm("fma.rn.f32x2 %0, %1, %2, %3;" : "=l"(d) : "l"(a), "l"(b), "l"(c));
    return d;
}
__device__ __forceinline__ ull f2add(ull a, ull b) {
    ull d;
    asm("add.rn.f32x2 %0, %1, %2;" : "=l"(d) : "l"(a), "l"(b));
    return d;
}
__device__ __forceinline__ void upk(ull v, float& lo, float& hi) {
    unsigned ulo, uhi;
    asm("mov.b64 {%0, %1}, %2;" : "=r"(ulo), "=r"(uhi) : "l"(v));
    lo = __uint_as_float(ulo); hi = __uint_as_float(uhi);
}

// ---------------------------------------------------------------------------
// Kernel 0: build E. grid = H_ (j), block = H_ (k). 16.8M MACs — negligible.
// ---------------------------------------------------------------------------
__global__ __launch_bounds__(H_) void compute_E_kernel(
    const float* __restrict__ W1,   // (65, 512)
    const float* __restrict__ W2,   // (512, 512)
    const float* __restrict__ W3)   // (512, 64)
{
    __shared__ float w1col[D_];
    const int j = blockIdx.x;
    const int k = threadIdx.x;
    if (k < D_) w1col[k] = W1[k * H_ + j];
    __syncthreads();

    float r[D_];
    const float4* w3r = (const float4*)(W3 + k * D_);
#pragma unroll
    for (int q = 0; q < D_ / 4; q++) {
        float4 v = w3r[q];
        r[4*q+0] = v.x; r[4*q+1] = v.y; r[4*q+2] = v.z; r[4*q+3] = v.w;
    }
    float acc = 0.f;
#pragma unroll
    for (int m = 0; m < D_; m++) acc = fmaf(w1col[m], r[m], acc);

    g_E[j * H_ + k] = W2[j * H_ + k] * acc;
}

// ---------------------------------------------------------------------------
// Main kernel. 16 samples (8 f32x2 pairs) per block, 512 threads.
// Phase-2 thread mapping: kt = tid&127 (4 k-cols), pg = (tid>>7)&1
// (pairs 4pg..4pg+3), qj = tid>>8 (j-half). Each group reads only its
// 256-row slice of W2/E; qj halves reduced through smem afterwards.
// Dyn smem (u64): h0[65*8] | hb[512*10] | tb[512*10] | h2b[512*10] | dvsh[32]
// hb/tb double as the z/a partial-reduction scratch after the mainloop.
// ---------------------------------------------------------------------------
__global__ __launch_bounds__(NT, 1) void cnf_main_kernel(
    const float* __restrict__ t,  const float* __restrict__ x,
    const float* __restrict__ W1, const float* __restrict__ b1,
    const float* __restrict__ W2, const float* __restrict__ b2,
    const float* __restrict__ W3, const float* __restrict__ b3,
    float* __restrict__ out)
{
    extern __shared__ ull sm[];
    ull* h0   = sm;                 // 520
    ull* hb   = h0 + 65 * 8;        // 5120
    ull* tb   = hb + 512 * 10;      // 5120
    ull* h2b  = tb + 512 * 10;      // 5120
    ull* dvsh = h2b + 512 * 10;     // 32

    const int tid = threadIdx.x;
    const int s0  = blockIdx.x * BT;

    // ---- load x tile (+t), layout [i][s] ----
    float* h0f = (float*)h0;
    for (int idx = tid; idx < BT * (D_ + 1); idx += NT) {
        int s = idx / (D_ + 1);
        int i = idx - s * (D_ + 1);
        float v = (i < D_) ? x[(size_t)(s0 + s) * (D_ + 1) + i] : t[0];
        h0f[i * BT + s] = v;
    }
    __syncthreads();

    // ---- Phase 1: h1 = tanh(x @ W1 + b1); t1 = h1^2 - 1 ----
    {
        const int j = tid;
        ull acc[8];
#pragma unroll
        for (int p = 0; p < 8; p++) acc[p] = 0ull;

#pragma unroll 5
        for (int i = 0; i < D_ + 1; i++) {
            ull wd = dup2(W1[i * H_ + j]);
            const ulonglong2* hp = (const ulonglong2*)(h0 + i * 8);
#pragma unroll
            for (int c = 0; c < 4; c++) {
                ulonglong2 hv = hp[c];
                acc[2*c]   = f2fma(hv.x, wd, acc[2*c]);
                acc[2*c+1] = f2fma(hv.y, wd, acc[2*c+1]);
            }
        }
        float b = b1[j];
#pragma unroll
        for (int p = 0; p < 8; p++) {
            float zl, zh; upk(acc[p], zl, zh);
            float hl = tanhf(zl + b), hh = tanhf(zh + b);
            hb[j * 10 + p] = pk2(hl, hh);
            tb[j * 10 + p] = pk2(fmaf(hl, hl, -1.f), fmaf(hh, hh, -1.f));
        }
    }
    __syncthreads();

    // ---- Phase 2 mainloop: z = h1@W2, a' = t1@E over this thread's slice ----
    const int kt = tid & 127;
    const int k0 = kt * 4;
    const int pg = (tid >> 7) & 1;      // pairs 4pg..4pg+3
    const int qj = tid >> 8;            // j in [qj*256, qj*256+256)

    ull z2[4][4], a2[4][4];             // [pair][k]
#pragma unroll
    for (int p = 0; p < 4; p++)
#pragma unroll
        for (int c = 0; c < 4; c++) { z2[p][c] = 0ull; a2[p][c] = 0ull; }

    {
        const int jbeg = qj * 256;
        const float* w_ptr = W2  + (size_t)jbeg * H_ + k0;
        const float* e_ptr = g_E + (size_t)jbeg * H_ + k0;
        const ull*   hbp   = hb + jbeg * 10 + 4 * pg;
        const ull*   tbp   = tb + jbeg * 10 + 4 * pg;

        float4 wc = *(const float4*)w_ptr;
        float4 ec = *(const float4*)e_ptr;

#pragma unroll 4
        for (int jj = 0; jj < 256; jj++) {
            // prefetch next j's weights
            float4 wn, en;
            if (jj < 255) {
                wn = *(const float4*)(w_ptr + (jj + 1) * H_);
                en = *(const float4*)(e_ptr + (jj + 1) * H_);
            }
            ulonglong2 hA = *(const ulonglong2*)(hbp + jj * 10);
            ulonglong2 hB = *(const ulonglong2*)(hbp + jj * 10 + 2);
            ulonglong2 tA = *(const ulonglong2*)(tbp + jj * 10);
            ulonglong2 tB = *(const ulonglong2*)(tbp + jj * 10 + 2);
            ull hp[4] = {hA.x, hA.y, hB.x, hB.y};
            ull tp[4] = {tA.x, tA.y, tB.x, tB.y};
            ull wd[4] = {dup2(wc.x), dup2(wc.y), dup2(wc.z), dup2(wc.w)};
            ull ed[4] = {dup2(ec.x), dup2(ec.y), dup2(ec.z), dup2(ec.w)};
#pragma unroll
            for (int p = 0; p < 4; p++)
#pragma unroll
                for (int c = 0; c < 4; c++) {
                    z2[p][c] = f2fma(hp[p], wd[c], z2[p][c]);
                    a2[p][c] = f2fma(tp[p], ed[c], a2[p][c]);
                }
            wc = wn; ec = en;
        }
    }
    __syncthreads();   // all reads of hb/tb done; safe to overwrite as scratch

    // ---- reduce the two j-halves: qj=1 dumps partials, qj=0 accumulates ----
    {
        ull* zscr = hb;   // 256 threads * 16 u64 = 4096 <= 5120
        ull* ascr = tb;
        if (qj == 1) {
            const int idx = tid - 256;
            ulonglong2* zd = (ulonglong2*)(zscr + idx * 16);
            ulonglong2* ad = (ulonglong2*)(ascr + idx * 16);
#pragma unroll
            for (int p = 0; p < 4; p++) {
                zd[2*p]   = make_ulonglong2(z2[p][0], z2[p][1]);
                zd[2*p+1] = make_ulonglong2(z2[p][2], z2[p][3]);
                ad[2*p]   = make_ulonglong2(a2[p][0], a2[p][1]);
                ad[2*p+1] = make_ulonglong2(a2[p][2], a2[p][3]);
            }
        }
        __syncthreads();
        if (qj == 0) {
            const ulonglong2* zs = (const ulonglong2*)(zscr + tid * 16);
            const ulonglong2* as = (const ulonglong2*)(ascr + tid * 16);
#pragma unroll
            for (int p = 0; p < 4; p++) {
                ulonglong2 za = zs[2*p], zb = zs[2*p+1];
                ulonglong2 aa = as[2*p], ab = as[2*p+1];
                z2[p][0] = f2add(z2[p][0], za.x);
                z2[p][1] = f2add(z2[p][1], za.y);
                z2[p][2] = f2add(z2[p][2], zb.x);
                z2[p][3] = f2add(z2[p][3], zb.y);
                a2[p][0] = f2add(a2[p][0], aa.x);
                a2[p][1] = f2add(a2[p][1], aa.y);
                a2[p][2] = f2add(a2[p][2], ab.x);
                a2[p][3] = f2add(a2[p][3], ab.y);
            }
        }
    }
    __syncthreads();   // scratch reads done; hb/tb dead from here

    // ---- Phase 2 epilogue (qj==0 threads): tanh, divergence, stash h2 ----
    if (qj == 0) {
        const ull NEG1 = dup2(-1.f);
        float4 b4 = *(const float4*)(b2 + k0);
        float bv[4] = {b4.x, b4.y, b4.z, b4.w};
        ull dv[4] = {0ull, 0ull, 0ull, 0ull};
#pragma unroll
        for (int c = 0; c < 4; c++)
#pragma unroll
            for (int p = 0; p < 4; p++) {
                float zl, zh; upk(z2[p][c], zl, zh);
                float hl = tanhf(zl + bv[c]), hh = tanhf(zh + bv[c]);
                ull hv = pk2(hl, hh);
                ull v2 = f2fma(hv, hv, NEG1);          // h2^2 - 1
                dv[p]  = f2fma(a2[p][c], v2, dv[p]);   // a'*v' == a*v
                h2b[(k0 + c) * 10 + 4 * pg + p] = hv;
            }
        // reduce over the 32 kt-lanes of this warp (distinct k ranges)
#pragma unroll
        for (int off = 16; off; off >>= 1)
#pragma unroll
            for (int p = 0; p < 4; p++)
                dv[p] = f2add(dv[p], __shfl_xor_sync(0xffffffffu, dv[p], off));
        if ((tid & 31) == 0) {
            int w = tid >> 5;   // 0..7 ; warps 0-3 pg0, 4-7 pg1
#pragma unroll
            for (int p = 0; p < 4; p++) dvsh[w * 4 + p] = dv[p];
        }
    }
    __syncthreads();

    // ---- Phase 3: out = (h2 @ W3 + b3)/2, plus div column ----
    {
        const int p = tid >> 6;    // sample pair 0..7
        const int m = tid & 63;    // output column
        ull o2 = 0ull;
#pragma unroll 4
        for (int k = 0; k < H_; k++) {
            ull hv = h2b[k * 10 + p];
            o2 = f2fma(hv, dup2(W3[k * D_ + m]), o2);
        }
        float ol, oh; upk(o2, ol, oh);
        float bm = b3[m];
        out[(size_t)(s0 + 2*p    ) * (D_ + 1) + m] = 0.5f * (ol + bm);
        out[(size_t)(s0 + 2*p + 1) * (D_ + 1) + m] = 0.5f * (oh + bm);
    }
    if (tid < BT) {
        int s    = tid;
        int pair = s >> 1, half = s & 1;
        int pgg  = pair >> 2, pw = pair & 3;
        float d = 0.f;
#pragma unroll
        for (int w = pgg * 4; w < pgg * 4 + 4; w++) {
            float lo, hi; upk(dvsh[w * 4 + pw], lo, hi);
            d += half ? hi : lo;
        }
        out[(size_t)(s0 + s) * (D_ + 1) + D_] = 0.5f * d;
    }
}

#define SMEM_BYTES ((65*8 + 3*512*10 + 32) * 8)

extern "C" void kernel_launch(void* const* d_in, const int* in_sizes, int n_in,
                              void* d_out, int out_size) {
    const float* t  = (const float*)d_in[0];
    const float* x  = (const float*)d_in[1];
    const float* W1 = (const float*)d_in[2];
    const float* b1 = (const float*)d_in[3];
    const float* W2 = (const float*)d_in[4];
    const float* b2 = (const float*)d_in[5];
    const float* W3 = (const float*)d_in[6];
    const float* b3 = (const float*)d_in[7];
    float* out = (float*)d_out;

    cudaFuncSetAttribute(cnf_main_kernel,
                         cudaFuncAttributeMaxDynamicSharedMemorySize, SMEM_BYTES);

    compute_E_kernel<<<H_, H_>>>(W1, W2, W3);
    cnf_main_kernel<<<B_ / BT, NT, SMEM_BYTES>>>(t, x, W1, b1, W2, b2, W3, b3, out);
}

// round 6
// speedup vs baseline: 1.8384x; 1.4369x over previous
#include <cuda_runtime.h>
#include <math.h>
#include <stdint.h>

#define B_  2048
#define D_  64
#define H_  512

// ---------------- intermediates (no allocation allowed) ----------------
__device__ __align__(256) float g_W2r[H_ * H_];   // rtf32(W2[j][k])
__device__ __align__(256) float g_Er [H_ * H_];   // rtf32(E[j][k])
__device__ __align__(256) float g_h1 [B_ * H_];   // rtf32(h1[s][j])
__device__ __align__(256) float g_t1 [B_ * H_];   // rtf32(h1^2-1)
__device__ __align__(256) float g_h2 [B_ * H_];   // h2[s][k] fp32
__device__ __align__(256) float g_divp[16 * B_];  // div partials

// ---------------- helpers ----------------
__device__ __forceinline__ uint32_t smem_u32(const void* p) {
    uint32_t a;
    asm("{ .reg .u64 t; cvta.to.shared.u64 t, %1; cvt.u32.u64 %0, t; }"
        : "=r"(a) : "l"(p));
    return a;
}
__device__ __forceinline__ float rtf32(float v) {
    uint32_t r;
    asm("cvt.rna.tf32.f32 %0, %1;" : "=r"(r) : "f"(v));
    return __uint_as_float(r);
}
__device__ __forceinline__ void mma_tf32(float* d, const uint32_t* a, const uint32_t* b) {
    asm volatile(
        "mma.sync.aligned.m16n8k8.row.col.f32.tf32.tf32.f32 "
        "{%0,%1,%2,%3}, {%4,%5,%6,%7}, {%8,%9}, {%0,%1,%2,%3};"
        : "+f"(d[0]), "+f"(d[1]), "+f"(d[2]), "+f"(d[3])
        : "r"(a[0]), "r"(a[1]), "r"(a[2]), "r"(a[3]), "r"(b[0]), "r"(b[1]));
}
#define CP_ASYNC16(dst, src) \
    asm volatile("cp.async.ca.shared.global [%0], [%1], 16;" :: "r"(dst), "l"(src))
#define CP_COMMIT() asm volatile("cp.async.commit_group;" ::: "memory")

// ---------------------------------------------------------------------------
// Kernel 1: prep — g_Er[j][k] = rtf32(W2[j][k]*sum_m W1[m][j]W3[k][m]),
//           g_W2r[j][k] = rtf32(W2[j][k]).  grid 64, block 512 (thread = k).
// ---------------------------------------------------------------------------
__global__ __launch_bounds__(512) void prep_kernel(
    const float* __restrict__ W1, const float* __restrict__ W2,
    const float* __restrict__ W3)
{
    extern __shared__ float ps[];          // w3s[512*65] | w1s[8*64]
    float* w3s = ps;
    float* w1s = ps + 512 * 65;
    const int tid = threadIdx.x;
    const int jb  = blockIdx.x * 8;

    for (int idx = tid; idx < H_ * D_; idx += 512) {
        int k = idx >> 6, m = idx & 63;
        w3s[k * 65 + m] = W3[idx];
    }
    for (int idx = tid; idx < 8 * D_; idx += 512) {
        int jj = idx >> 6, m = idx & 63;
        w1s[jj * 64 + m] = W1[m * H_ + jb + jj];
    }
    __syncthreads();

    const int k = tid;
    float acc[8] = {0,0,0,0,0,0,0,0};
#pragma unroll 8
    for (int m = 0; m < D_; m++) {
        float w3v = w3s[k * 65 + m];
#pragma unroll
        for (int jj = 0; jj < 8; jj++) acc[jj] = fmaf(w1s[jj * 64 + m], w3v, acc[jj]);
    }
#pragma unroll
    for (int jj = 0; jj < 8; jj++) {
        int j = jb + jj;
        float w2 = W2[j * H_ + k];
        g_Er [j * H_ + k] = rtf32(w2 * acc[jj]);
        g_W2r[j * H_ + k] = rtf32(w2);
    }
}

// ---------------------------------------------------------------------------
// Kernel 2: phase 1 — h1/t1 for 16 samples per block. 128 blocks x 512 thr.
// ---------------------------------------------------------------------------
__global__ __launch_bounds__(512) void phase1_kernel(
    const float* __restrict__ t, const float* __restrict__ x,
    const float* __restrict__ W1, const float* __restrict__ b1)
{
    __shared__ float xs[65][16];
    const int tid = threadIdx.x;
    const int s0  = blockIdx.x * 16;

    for (int idx = tid; idx < 65 * 16; idx += 512) {
        int i = idx >> 4, s = idx & 15;
        xs[i][s] = (i < D_) ? x[(size_t)(s0 + s) * 65 + i] : t[0];
    }
    __syncthreads();

    const int j = tid;
    float acc[16];
#pragma unroll
    for (int s = 0; s < 16; s++) acc[s] = 0.f;
#pragma unroll 5
    for (int i = 0; i < 65; i++) {
        float w = W1[i * H_ + j];
#pragma unroll
        for (int s = 0; s < 16; s++) acc[s] = fmaf(xs[i][s], w, acc[s]);
    }
    float bj = b1[j];
#pragma unroll
    for (int s = 0; s < 16; s++) {
        float h = tanhf(acc[s] + bj);
        g_h1[(size_t)(s0 + s) * H_ + j] = rtf32(h);
        g_t1[(size_t)(s0 + s) * H_ + j] = rtf32(fmaf(h, h, -1.f));
    }
}

// ---------------------------------------------------------------------------
// Kernel 3: tf32 mma.sync double-GEMM.
//   grid (16 stiles, 8 ntiles), 128 thr = 4 warps (2m x 2n), warp tile 64x32.
//   z = h1 @ W2 (acc z), a = t1 @ E (acc a); K chunks of 32, cp.async 2-stage.
//   Epilogue: h2 = tanh(z + b2) -> g_h2[s][k]; div partials -> g_divp.
// Smem floats per stage: Ah[128*36] At[128*36] Bw[32*72] Be[32*72] = 13824.
// ---------------------------------------------------------------------------
#define STG_F 13824
__global__ __launch_bounds__(128, 1) void gemm2_kernel(const float* __restrict__ b2)
{
    extern __shared__ float sf[];
    const int tid  = threadIdx.x;
    const int lane = tid & 31, wid = tid >> 5;
    const int warpm = wid >> 1, warpn = wid & 1;
    const int stile = blockIdx.x, ntile = blockIdx.y;

    auto issue_chunk = [&](int kc, int st) {
        uint32_t sbase = smem_u32(sf + st * STG_F);
#pragma unroll
        for (int mm = 0; mm < 2; mm++) {
            const float* s = (mm ? g_t1 : g_h1) + (size_t)(stile * 128) * H_ + kc * 32;
            uint32_t d = sbase + mm * 4608 * 4;
#pragma unroll
            for (int i = 0; i < 8; i++) {
                int idx = i * 128 + tid;
                int row = idx >> 3, qc = idx & 7;
                CP_ASYNC16(d + (row * 36 + qc * 4) * 4, s + (size_t)row * H_ + qc * 4);
            }
        }
#pragma unroll
        for (int mm = 0; mm < 2; mm++) {
            const float* s = (mm ? g_Er : g_W2r) + (size_t)(kc * 32) * H_ + ntile * 64;
            uint32_t d = sbase + (9216 + mm * 2304) * 4;
#pragma unroll
            for (int i = 0; i < 4; i++) {
                int idx = i * 128 + tid;
                int row = idx >> 4, qc = idx & 15;
                CP_ASYNC16(d + (row * 72 + qc * 4) * 4, s + (size_t)row * H_ + qc * 4);
            }
        }
        CP_COMMIT();
    };

    float accz[4][4][4], acca[4][4][4];
#pragma unroll
    for (int ms = 0; ms < 4; ms++)
#pragma unroll
        for (int ns = 0; ns < 4; ns++)
#pragma unroll
            for (int c = 0; c < 4; c++) { accz[ms][ns][c] = 0.f; acca[ms][ns][c] = 0.f; }

    issue_chunk(0, 0);
    for (int kc = 0; kc < 16; kc++) {
        if (kc < 15) {
            issue_chunk(kc + 1, (kc + 1) & 1);
            asm volatile("cp.async.wait_group 1;" ::: "memory");
        } else {
            asm volatile("cp.async.wait_group 0;" ::: "memory");
        }
        __syncthreads();
        const float* S  = sf + (kc & 1) * STG_F;
        const float* Ah = S, *At = S + 4608, *Bw = S + 9216, *Be = S + 11520;

#pragma unroll
        for (int ks = 0; ks < 4; ks++) {
            uint32_t bw[4][2], be[4][2];
#pragma unroll
            for (int ns = 0; ns < 4; ns++) {
                int col = warpn * 32 + ns * 8 + (lane >> 2);
                int r0  = ks * 8 + (lane & 3);
                bw[ns][0] = __float_as_uint(Bw[r0 * 72 + col]);
                bw[ns][1] = __float_as_uint(Bw[(r0 + 4) * 72 + col]);
                be[ns][0] = __float_as_uint(Be[r0 * 72 + col]);
                be[ns][1] = __float_as_uint(Be[(r0 + 4) * 72 + col]);
            }
#pragma unroll
            for (int ms = 0; ms < 4; ms++) {
                int row = warpm * 64 + ms * 16 + (lane >> 2);
                int c0  = ks * 8 + (lane & 3);
                uint32_t ah[4], at[4];
                ah[0] = __float_as_uint(Ah[row * 36 + c0]);
                ah[1] = __float_as_uint(Ah[(row + 8) * 36 + c0]);
                ah[2] = __float_as_uint(Ah[row * 36 + c0 + 4]);
                ah[3] = __float_as_uint(Ah[(row + 8) * 36 + c0 + 4]);
                at[0] = __float_as_uint(At[row * 36 + c0]);
                at[1] = __float_as_uint(At[(row + 8) * 36 + c0]);
                at[2] = __float_as_uint(At[row * 36 + c0 + 4]);
                at[3] = __float_as_uint(At[(row + 8) * 36 + c0 + 4]);
#pragma unroll
                for (int ns = 0; ns < 4; ns++) {
                    mma_tf32(accz[ms][ns], ah, bw[ns]);
                    mma_tf32(acca[ms][ns], at, be[ns]);
                }
            }
        }
        __syncthreads();
    }

    // ---- epilogue: tanh, h2 out, divergence partials ----
    float dv[4][2];
#pragma unroll
    for (int ms = 0; ms < 4; ms++) { dv[ms][0] = 0.f; dv[ms][1] = 0.f; }

#pragma unroll
    for (int ms = 0; ms < 4; ms++)
#pragma unroll
        for (int ns = 0; ns < 4; ns++)
#pragma unroll
            for (int c = 0; c < 4; c++) {
                int row = stile * 128 + warpm * 64 + ms * 16 + (lane >> 2) + ((c >> 1) ? 8 : 0);
                int col = ntile * 64 + warpn * 32 + ns * 8 + 2 * (lane & 3) + (c & 1);
                float h2 = tanhf(accz[ms][ns][c] + b2[col]);
                g_h2[(size_t)row * H_ + col] = h2;
                dv[ms][c >> 1] = fmaf(acca[ms][ns][c], fmaf(h2, h2, -1.f), dv[ms][c >> 1]);
            }
#pragma unroll
    for (int ms = 0; ms < 4; ms++)
#pragma unroll
        for (int h = 0; h < 2; h++) {
            float v = dv[ms][h];
            v += __shfl_xor_sync(0xffffffffu, v, 1);
            v += __shfl_xor_sync(0xffffffffu, v, 2);
            if ((lane & 3) == 0) {
                int s = stile * 128 + warpm * 64 + ms * 16 + (lane >> 2) + h * 8;
                g_divp[(ntile * 2 + warpn) * B_ + s] = v;
            }
        }
}

// ---------------------------------------------------------------------------
// Kernel 4: phase 3 — out = (h2 @ W3 + b3)/2, div column. 128 blk x 512 thr.
// ---------------------------------------------------------------------------
__global__ __launch_bounds__(512) void phase3_kernel(
    const float* __restrict__ W3, const float* __restrict__ b3,
    float* __restrict__ out)
{
    const int tid = threadIdx.x;
    const int s0  = blockIdx.x * 16;
    const int m   = tid & 63;
    const int sg  = tid >> 6;            // 0..7
    const int sA  = s0 + sg, sB = s0 + sg + 8;

    float o0 = 0.f, o1 = 0.f;
#pragma unroll 8
    for (int k = 0; k < H_; k++) {
        float w = W3[k * D_ + m];
        o0 = fmaf(g_h2[(size_t)sA * H_ + k], w, o0);
        o1 = fmaf(g_h2[(size_t)sB * H_ + k], w, o1);
    }
    float bm = b3[m];
    out[(size_t)sA * 65 + m] = 0.5f * (o0 + bm);
    out[(size_t)sB * 65 + m] = 0.5f * (o1 + bm);

    if (tid < 16) {
        int s = s0 + tid;
        float d = 0.f;
#pragma unroll
        for (int p = 0; p < 16; p++) d += g_divp[p * B_ + s];
        out[(size_t)s * 65 + D_] = 0.5f * d;
    }
}

// ---------------------------------------------------------------------------
extern "C" void kernel_launch(void* const* d_in, const int* in_sizes, int n_in,
                              void* d_out, int out_size) {
    const float* t  = (const float*)d_in[0];
    const float* x  = (const float*)d_in[1];
    const float* W1 = (const float*)d_in[2];
    const float* b1 = (const float*)d_in[3];
    const float* W2 = (const float*)d_in[4];
    const float* b2 = (const float*)d_in[5];
    const float* W3 = (const float*)d_in[6];
    const float* b3 = (const float*)d_in[7];
    float* out = (float*)d_out;

    const int prep_smem = (512 * 65 + 8 * 64) * 4;
    const int gemm_smem = 2 * STG_F * 4;     // 110592 B
    cudaFuncSetAttribute(prep_kernel,  cudaFuncAttributeMaxDynamicSharedMemorySize, prep_smem);
    cudaFuncSetAttribute(gemm2_kernel, cudaFuncAttributeMaxDynamicSharedMemorySize, gemm_smem);

    prep_kernel<<<64, 512, prep_smem>>>(W1, W2, W3);
    phase1_kernel<<<B_ / 16, 512>>>(t, x, W1, b1);
    gemm2_kernel<<<dim3(B_ / 128, H_ / 64), 128, gemm_smem>>>(b2);
    phase3_kernel<<<B_ / 16, 512>>>(W3, b3, out);
}

// round 11
// speedup vs baseline: 2.4880x; 1.3534x over previous
#include <cuda_runtime.h>
#include <math.h>
#include <stdint.h>

#define B_  2048
#define D_  64
#define H_  512

// ---------------- intermediates (no allocation allowed) ----------------
__device__ __align__(256) float g_W2r[H_ * H_];   // rtf32(W2[j][k])
__device__ __align__(256) float g_Er [H_ * H_];   // rtf32(E[j][k])
__device__ __align__(256) float g_h1 [B_ * H_];   // rtf32(h1[s][j])
__device__ __align__(256) float g_t1 [B_ * H_];   // rtf32(h1^2-1)
__device__ __align__(256) float g_h2 [B_ * H_];   // h2[s][k] fp32
__device__ __align__(256) float g_divp[16 * B_];  // div partials

// ---------------- helpers ----------------
__device__ __forceinline__ uint32_t smem_u32(const void* p) {
    uint32_t a;
    asm("{ .reg .u64 t; cvta.to.shared.u64 t, %1; cvt.u32.u64 %0, t; }"
        : "=r"(a) : "l"(p));
    return a;
}
__device__ __forceinline__ float rtf32(float v) {
    uint32_t r;
    asm("cvt.rna.tf32.f32 %0, %1;" : "=r"(r) : "f"(v));
    return __uint_as_float(r);
}
__device__ __forceinline__ void mma_tf32(float* d, const uint32_t* a, const uint32_t* b) {
    asm volatile(
        "mma.sync.aligned.m16n8k8.row.col.f32.tf32.tf32.f32 "
        "{%0,%1,%2,%3}, {%4,%5,%6,%7}, {%8,%9}, {%0,%1,%2,%3};"
        : "+f"(d[0]), "+f"(d[1]), "+f"(d[2]), "+f"(d[3])
        : "r"(a[0]), "r"(a[1]), "r"(a[2]), "r"(a[3]), "r"(b[0]), "r"(b[1]));
}
#define CP_ASYNC16(dst, src) \
    asm volatile("cp.async.ca.shared.global [%0], [%1], 16;" :: "r"(dst), "l"(src))
#define CP_COMMIT() asm volatile("cp.async.commit_group;" ::: "memory")

// ---------------------------------------------------------------------------
// Kernel 1: prep — g_Er[j][k] = rtf32(W2[j][k]*sum_m W1[m][j]W3[k][m]),
//           g_W2r[j][k] = rtf32(W2[j][k]).  grid 64, block 512 (thread = k).
// ---------------------------------------------------------------------------
__global__ __launch_bounds__(512) void prep_kernel(
    const float* __restrict__ W1, const float* __restrict__ W2,
    const float* __restrict__ W3)
{
    extern __shared__ float ps[];          // w3s[512*65] | w1s[8*64]
    float* w3s = ps;
    float* w1s = ps + 512 * 65;
    const int tid = threadIdx.x;
    const int jb  = blockIdx.x * 8;

    for (int idx = tid; idx < H_ * D_; idx += 512) {
        int k = idx >> 6, m = idx & 63;
        w3s[k * 65 + m] = W3[idx];
    }
    for (int idx = tid; idx < 8 * D_; idx += 512) {
        int jj = idx >> 6, m = idx & 63;
        w1s[jj * 64 + m] = W1[m * H_ + jb + jj];
    }
    __syncthreads();

    const int k = tid;
    float acc[8] = {0,0,0,0,0,0,0,0};
#pragma unroll 8
    for (int m = 0; m < D_; m++) {
        float w3v = w3s[k * 65 + m];
#pragma unroll
        for (int jj = 0; jj < 8; jj++) acc[jj] = fmaf(w1s[jj * 64 + m], w3v, acc[jj]);
    }
#pragma unroll
    for (int jj = 0; jj < 8; jj++) {
        int j = jb + jj;
        float w2 = W2[j * H_ + k];
        g_Er [j * H_ + k] = rtf32(w2 * acc[jj]);
        g_W2r[j * H_ + k] = rtf32(w2);
    }
}

// ---------------------------------------------------------------------------
// Kernel 2: phase 1 — h1/t1 for 16 samples per block. 128 blocks x 512 thr.
// ---------------------------------------------------------------------------
__global__ __launch_bounds__(512) void phase1_kernel(
    const float* __restrict__ t, const float* __restrict__ x,
    const float* __restrict__ W1, const float* __restrict__ b1)
{
    __shared__ float xs[65][16];
    const int tid = threadIdx.x;
    const int s0  = blockIdx.x * 16;

    for (int idx = tid; idx < 65 * 16; idx += 512) {
        int i = idx >> 4, s = idx & 15;
        xs[i][s] = (i < D_) ? x[(size_t)(s0 + s) * 65 + i] : t[0];
    }
    __syncthreads();

    const int j = tid;
    float acc[16];
#pragma unroll
    for (int s = 0; s < 16; s++) acc[s] = 0.f;
#pragma unroll 5
    for (int i = 0; i < 65; i++) {
        float w = W1[i * H_ + j];
#pragma unroll
        for (int s = 0; s < 16; s++) acc[s] = fmaf(xs[i][s], w, acc[s]);
    }
    float bj = b1[j];
#pragma unroll
    for (int s = 0; s < 16; s++) {
        float h = tanhf(acc[s] + bj);
        g_h1[(size_t)(s0 + s) * H_ + j] = rtf32(h);
        g_t1[(size_t)(s0 + s) * H_ + j] = rtf32(fmaf(h, h, -1.f));
    }
}

// ---------------------------------------------------------------------------
// Kernel 3: tf32 mma.sync double-GEMM.
//   grid (16 stiles, 8 ntiles), 128 thr = 4 warps (2m x 2n), warp tile 64x32.
//   z = h1 @ W2 (acc z), a = t1 @ E (acc a); K chunks of 32, cp.async 2-stage.
//   Epilogue: h2 = tanh(z + b2) -> g_h2[s][k]; div partials -> g_divp.
// Smem floats per stage: Ah[128*36] At[128*36] Bw[32*72] Be[32*72] = 13824.
// ---------------------------------------------------------------------------
#define STG_F 13824
__global__ __launch_bounds__(128, 1) void gemm2_kernel(const float* __restrict__ b2)
{
    extern __shared__ float sf[];
    const int tid  = threadIdx.x;
    const int lane = tid & 31, wid = tid >> 5;
    const int warpm = wid >> 1, warpn = wid & 1;
    const int stile = blockIdx.x, ntile = blockIdx.y;

    auto issue_chunk = [&](int kc, int st) {
        uint32_t sbase = smem_u32(sf + st * STG_F);
#pragma unroll
        for (int mm = 0; mm < 2; mm++) {
            const float* s = (mm ? g_t1 : g_h1) + (size_t)(stile * 128) * H_ + kc * 32;
            uint32_t d = sbase + mm * 4608 * 4;
#pragma unroll
            for (int i = 0; i < 8; i++) {
                int idx = i * 128 + tid;
                int row = idx >> 3, qc = idx & 7;
                CP_ASYNC16(d + (row * 36 + qc * 4) * 4, s + (size_t)row * H_ + qc * 4);
            }
        }
#pragma unroll
        for (int mm = 0; mm < 2; mm++) {
            const float* s = (mm ? g_Er : g_W2r) + (size_t)(kc * 32) * H_ + ntile * 64;
            uint32_t d = sbase + (9216 + mm * 2304) * 4;
#pragma unroll
            for (int i = 0; i < 4; i++) {
                int idx = i * 128 + tid;
                int row = idx >> 4, qc = idx & 15;
                CP_ASYNC16(d + (row * 72 + qc * 4) * 4, s + (size_t)row * H_ + qc * 4);
            }
        }
        CP_COMMIT();
    };

    float accz[4][4][4], acca[4][4][4];
#pragma unroll
    for (int ms = 0; ms < 4; ms++)
#pragma unroll
        for (int ns = 0; ns < 4; ns++)
#pragma unroll
            for (int c = 0; c < 4; c++) { accz[ms][ns][c] = 0.f; acca[ms][ns][c] = 0.f; }

    issue_chunk(0, 0);
    for (int kc = 0; kc < 16; kc++) {
        if (kc < 15) {
            issue_chunk(kc + 1, (kc + 1) & 1);
            asm volatile("cp.async.wait_group 1;" ::: "memory");
        } else {
            asm volatile("cp.async.wait_group 0;" ::: "memory");
        }
        __syncthreads();
        const float* S  = sf + (kc & 1) * STG_F;
        const float* Ah = S, *At = S + 4608, *Bw = S + 9216, *Be = S + 11520;

#pragma unroll
        for (int ks = 0; ks < 4; ks++) {
            uint32_t bw[4][2], be[4][2];
#pragma unroll
            for (int ns = 0; ns < 4; ns++) {
                int col = warpn * 32 + ns * 8 + (lane >> 2);
                int r0  = ks * 8 + (lane & 3);
                bw[ns][0] = __float_as_uint(Bw[r0 * 72 + col]);
                bw[ns][1] = __float_as_uint(Bw[(r0 + 4) * 72 + col]);
                be[ns][0] = __float_as_uint(Be[r0 * 72 + col]);
                be[ns][1] = __float_as_uint(Be[(r0 + 4) * 72 + col]);
            }
#pragma unroll
            for (int ms = 0; ms < 4; ms++) {
                int row = warpm * 64 + ms * 16 + (lane >> 2);
                int c0  = ks * 8 + (lane & 3);
                uint32_t ah[4], at[4];
                ah[0] = __float_as_uint(Ah[row * 36 + c0]);
                ah[1] = __float_as_uint(Ah[(row + 8) * 36 + c0]);
                ah[2] = __float_as_uint(Ah[row * 36 + c0 + 4]);
                ah[3] = __float_as_uint(Ah[(row + 8) * 36 + c0 + 4]);
                at[0] = __float_as_uint(At[row * 36 + c0]);
                at[1] = __float_as_uint(At[(row + 8) * 36 + c0]);
                at[2] = __float_as_uint(At[row * 36 + c0 + 4]);
                at[3] = __float_as_uint(At[(row + 8) * 36 + c0 + 4]);
#pragma unroll
                for (int ns = 0; ns < 4; ns++) {
                    mma_tf32(accz[ms][ns], ah, bw[ns]);
                    mma_tf32(acca[ms][ns], at, be[ns]);
                }
            }
        }
        __syncthreads();
    }

    // ---- epilogue: tanh, h2 out, divergence partials ----
    float dv[4][2];
#pragma unroll
    for (int ms = 0; ms < 4; ms++) { dv[ms][0] = 0.f; dv[ms][1] = 0.f; }

#pragma unroll
    for (int ms = 0; ms < 4; ms++)
#pragma unroll
        for (int ns = 0; ns < 4; ns++)
#pragma unroll
            for (int c = 0; c < 4; c++) {
                int row = stile * 128 + warpm * 64 + ms * 16 + (lane >> 2) + ((c >> 1) ? 8 : 0);
                int col = ntile * 64 + warpn * 32 + ns * 8 + 2 * (lane & 3) + (c & 1);
                float h2 = tanhf(accz[ms][ns][c] + b2[col]);
                g_h2[(size_t)row * H_ + col] = h2;
                dv[ms][c >> 1] = fmaf(acca[ms][ns][c], fmaf(h2, h2, -1.f), dv[ms][c >> 1]);
            }
#pragma unroll
    for (int ms = 0; ms < 4; ms++)
#pragma unroll
        for (int h = 0; h < 2; h++) {
            float v = dv[ms][h];
            v += __shfl_xor_sync(0xffffffffu, v, 1);
            v += __shfl_xor_sync(0xffffffffu, v, 2);
            if ((lane & 3) == 0) {
                int s = stile * 128 + warpm * 64 + ms * 16 + (lane >> 2) + h * 8;
                g_divp[(ntile * 2 + warpn) * B_ + s] = v;
            }
        }
}

// ---------------------------------------------------------------------------
// Kernel 4: phase 3 — smem-tiled GEMM: out[s][m] = (h2[s][:]@W3[:][m]+b3)/2.
//   grid 64 (32 samples each), 256 threads = 8 warps.
//   K-chunks of 64: stage h2 (32x64) + W3 (64x64) in smem, float4 loads.
//   Thread (ty=tid>>5, tx=tid&31) owns samples ty*4..+3, cols tx*2, tx*2+1.
// ---------------------------------------------------------------------------
#define P3_BM 32
#define P3_KC 64
__global__ __launch_bounds__(256) void phase3_kernel(
    const float* __restrict__ W3, const float* __restrict__ b3,
    float* __restrict__ out)
{
    __shared__ float h2s[P3_BM][P3_KC + 4];
    __shared__ float w3s[P3_KC][D_ + 4];

    const int tid = threadIdx.x;
    const int tx  = tid & 31, ty = tid >> 5;
    const int s0  = blockIdx.x * P3_BM;

    float acc[4][2];
#pragma unroll
    for (int si = 0; si < 4; si++) { acc[si][0] = 0.f; acc[si][1] = 0.f; }

    for (int k0 = 0; k0 < H_; k0 += P3_KC) {
        // stage h2 tile: 32 rows x 64 k = 512 float4, 2 per thread
#pragma unroll
        for (int i = 0; i < 2; i++) {
            int idx = i * 256 + tid;             // 0..511
            int s = idx >> 4, q = idx & 15;
            float4 v = *(const float4*)(g_h2 + (size_t)(s0 + s) * H_ + k0 + q * 4);
            *(float4*)&h2s[s][q * 4] = v;
        }
        // stage W3 tile: 64 rows x 64 m = 1024 float4, 4 per thread
#pragma unroll
        for (int i = 0; i < 4; i++) {
            int idx = i * 256 + tid;             // 0..1023
            int kk = idx >> 4, q = idx & 15;
            float4 v = *(const float4*)(W3 + (size_t)(k0 + kk) * D_ + q * 4);
            *(float4*)&w3s[kk][q * 4] = v;
        }
        __syncthreads();

#pragma unroll 16
        for (int kk = 0; kk < P3_KC; kk++) {
            float2 w = *(const float2*)&w3s[kk][tx * 2];
#pragma unroll
            for (int si = 0; si < 4; si++) {
                float h = h2s[ty * 4 + si][kk];
                acc[si][0] = fmaf(h, w.x, acc[si][0]);
                acc[si][1] = fmaf(h, w.y, acc[si][1]);
            }
        }
        __syncthreads();
    }

    const float bm0 = b3[tx * 2], bm1 = b3[tx * 2 + 1];
#pragma unroll
    for (int si = 0; si < 4; si++) {
        int s = s0 + ty * 4 + si;
        float* op = out + (size_t)s * 65 + tx * 2;
        op[0] = 0.5f * (acc[si][0] + bm0);
        op[1] = 0.5f * (acc[si][1] + bm1);
    }
    if (tid < P3_BM) {
        int s = s0 + tid;
        float d = 0.f;
#pragma unroll
        for (int p = 0; p < 16; p++) d += g_divp[p * B_ + s];
        out[(size_t)s * 65 + D_] = 0.5f * d;
    }
}

// ---------------------------------------------------------------------------
extern "C" void kernel_launch(void* const* d_in, const int* in_sizes, int n_in,
                              void* d_out, int out_size) {
    const float* t  = (const float*)d_in[0];
    const float* x  = (const float*)d_in[1];
    const float* W1 = (const float*)d_in[2];
    const float* b1 = (const float*)d_in[3];
    const float* W2 = (const float*)d_in[4];
    const float* b2 = (const float*)d_in[5];
    const float* W3 = (const float*)d_in[6];
    const float* b3 = (const float*)d_in[7];
    float* out = (float*)d_out;

    const int prep_smem = (512 * 65 + 8 * 64) * 4;
    const int gemm_smem = 2 * STG_F * 4;     // 110592 B
    cudaFuncSetAttribute(prep_kernel,  cudaFuncAttributeMaxDynamicSharedMemorySize, prep_smem);
    cudaFuncSetAttribute(gemm2_kernel, cudaFuncAttributeMaxDynamicSharedMemorySize, gemm_smem);

    prep_kernel<<<64, 512, prep_smem>>>(W1, W2, W3);
    phase1_kernel<<<B_ / 16, 512>>>(t, x, W1, b1);
    gemm2_kernel<<<dim3(B_ / 128, H_ / 64), 128, gemm_smem>>>(b2);
    phase3_kernel<<<B_ / P3_BM, 256>>>(W3, b3, out);
}

// round 13
// speedup vs baseline: 2.6806x; 1.0774x over previous
#include <cuda_runtime.h>
#include <math.h>
#include <stdint.h>

#define B_  2048
#define D_  64
#define H_  512

// ---------------- intermediates (no allocation allowed) ----------------
__device__ __align__(256) float g_W2r[H_ * H_];   // rtf32(W2[j][k])
__device__ __align__(256) float g_Er [H_ * H_];   // rtf32(E[j][k])
__device__ __align__(256) float g_h1 [B_ * H_];   // rtf32(h1[s][j])
__device__ __align__(256) float g_t1 [B_ * H_];   // rtf32(h1^2-1)
__device__ __align__(256) float g_h2 [B_ * H_];   // h2[s][k] fp32
__device__ __align__(256) float g_divp[16 * B_];  // div partials

// ---------------- helpers ----------------
__device__ __forceinline__ uint32_t smem_u32(const void* p) {
    uint32_t a;
    asm("{ .reg .u64 t; cvta.to.shared.u64 t, %1; cvt.u32.u64 %0, t; }"
        : "=r"(a) : "l"(p));
    return a;
}
__device__ __forceinline__ float rtf32(float v) {
    uint32_t r;
    asm("cvt.rna.tf32.f32 %0, %1;" : "=r"(r) : "f"(v));
    return __uint_as_float(r);
}
__device__ __forceinline__ void mma_tf32(float* d, const uint32_t* a, const uint32_t* b) {
    asm volatile(
        "mma.sync.aligned.m16n8k8.row.col.f32.tf32.tf32.f32 "
        "{%0,%1,%2,%3}, {%4,%5,%6,%7}, {%8,%9}, {%0,%1,%2,%3};"
        : "+f"(d[0]), "+f"(d[1]), "+f"(d[2]), "+f"(d[3])
        : "r"(a[0]), "r"(a[1]), "r"(a[2]), "r"(a[3]), "r"(b[0]), "r"(b[1]));
}
#define CP_ASYNC16(dst, src) \
    asm volatile("cp.async.ca.shared.global [%0], [%1], 16;" :: "r"(dst), "l"(src))
#define CP_COMMIT() asm volatile("cp.async.commit_group;" ::: "memory")

// ---------------------------------------------------------------------------
// Kernel 1: prep — g_Er[j][k] = rtf32(W2[j][k]*sum_m W1[m][j]W3[k][m]),
//           g_W2r[j][k] = rtf32(W2[j][k]).  grid 64, block 512 (thread = k).
// ---------------------------------------------------------------------------
__global__ __launch_bounds__(512) void prep_kernel(
    const float* __restrict__ W1, const float* __restrict__ W2,
    const float* __restrict__ W3)
{
    extern __shared__ float ps[];          // w3s[512*65] | w1s[8*64]
    float* w3s = ps;
    float* w1s = ps + 512 * 65;
    const int tid = threadIdx.x;
    const int jb  = blockIdx.x * 8;

    for (int idx = tid; idx < H_ * D_; idx += 512) {
        int k = idx >> 6, m = idx & 63;
        w3s[k * 65 + m] = W3[idx];
    }
    for (int idx = tid; idx < 8 * D_; idx += 512) {
        int jj = idx >> 6, m = idx & 63;
        w1s[jj * 64 + m] = W1[m * H_ + jb + jj];
    }
    __syncthreads();

    const int k = tid;
    float acc[8] = {0,0,0,0,0,0,0,0};
#pragma unroll 8
    for (int m = 0; m < D_; m++) {
        float w3v = w3s[k * 65 + m];
#pragma unroll
        for (int jj = 0; jj < 8; jj++) acc[jj] = fmaf(w1s[jj * 64 + m], w3v, acc[jj]);
    }
#pragma unroll
    for (int jj = 0; jj < 8; jj++) {
        int j = jb + jj;
        float w2 = W2[j * H_ + k];
        g_Er [j * H_ + k] = rtf32(w2 * acc[jj]);
        g_W2r[j * H_ + k] = rtf32(w2);
    }
}

// ---------------------------------------------------------------------------
// Kernel 2: phase 1 — h1/t1 for 16 samples per block. 128 blocks x 512 thr.
// ---------------------------------------------------------------------------
__global__ __launch_bounds__(512) void phase1_kernel(
    const float* __restrict__ t, const float* __restrict__ x,
    const float* __restrict__ W1, const float* __restrict__ b1)
{
    __shared__ float xs[65][16];
    const int tid = threadIdx.x;
    const int s0  = blockIdx.x * 16;

    for (int idx = tid; idx < 65 * 16; idx += 512) {
        int i = idx >> 4, s = idx & 15;
        xs[i][s] = (i < D_) ? x[(size_t)(s0 + s) * 65 + i] : t[0];
    }
    __syncthreads();

    const int j = tid;
    float acc[16];
#pragma unroll
    for (int s = 0; s < 16; s++) acc[s] = 0.f;
#pragma unroll 5
    for (int i = 0; i < 65; i++) {
        float w = W1[i * H_ + j];
#pragma unroll
        for (int s = 0; s < 16; s++) acc[s] = fmaf(xs[i][s], w, acc[s]);
    }
    float bj = b1[j];
#pragma unroll
    for (int s = 0; s < 16; s++) {
        float h = tanhf(acc[s] + bj);
        g_h1[(size_t)(s0 + s) * H_ + j] = rtf32(h);
        g_t1[(size_t)(s0 + s) * H_ + j] = rtf32(fmaf(h, h, -1.f));
    }
}

// ---------------------------------------------------------------------------
// Kernel 3: tf32 mma.sync double-GEMM.
//   grid (16 stiles, 8 ntiles), 128 thr = 4 warps (2m x 2n), warp tile 64x32.
//   z = h1 @ W2 (acc z), a = t1 @ E (acc a); K chunks of 32, cp.async 2-stage.
//   Epilogue: h2 = tanh(z + b2) -> g_h2[s][k]; div partials -> g_divp.
// Smem floats per stage: Ah[128*36] At[128*36] Bw[32*72] Be[32*72] = 13824.
// ---------------------------------------------------------------------------
#define STG_F 13824
__global__ __launch_bounds__(128, 1) void gemm2_kernel(const float* __restrict__ b2)
{
    extern __shared__ float sf[];
    const int tid  = threadIdx.x;
    const int lane = tid & 31, wid = tid >> 5;
    const int warpm = wid >> 1, warpn = wid & 1;
    const int stile = blockIdx.x, ntile = blockIdx.y;

    auto issue_chunk = [&](int kc, int st) {
        uint32_t sbase = smem_u32(sf + st * STG_F);
#pragma unroll
        for (int mm = 0; mm < 2; mm++) {
            const float* s = (mm ? g_t1 : g_h1) + (size_t)(stile * 128) * H_ + kc * 32;
            uint32_t d = sbase + mm * 4608 * 4;
#pragma unroll
            for (int i = 0; i < 8; i++) {
                int idx = i * 128 + tid;
                int row = idx >> 3, qc = idx & 7;
                CP_ASYNC16(d + (row * 36 + qc * 4) * 4, s + (size_t)row * H_ + qc * 4);
            }
        }
#pragma unroll
        for (int mm = 0; mm < 2; mm++) {
            const float* s = (mm ? g_Er : g_W2r) + (size_t)(kc * 32) * H_ + ntile * 64;
            uint32_t d = sbase + (9216 + mm * 2304) * 4;
#pragma unroll
            for (int i = 0; i < 4; i++) {
                int idx = i * 128 + tid;
                int row = idx >> 4, qc = idx & 15;
                CP_ASYNC16(d + (row * 72 + qc * 4) * 4, s + (size_t)row * H_ + qc * 4);
            }
        }
        CP_COMMIT();
    };

    float accz[4][4][4], acca[4][4][4];
#pragma unroll
    for (int ms = 0; ms < 4; ms++)
#pragma unroll
        for (int ns = 0; ns < 4; ns++)
#pragma unroll
            for (int c = 0; c < 4; c++) { accz[ms][ns][c] = 0.f; acca[ms][ns][c] = 0.f; }

    issue_chunk(0, 0);
    for (int kc = 0; kc < 16; kc++) {
        if (kc < 15) {
            issue_chunk(kc + 1, (kc + 1) & 1);
            asm volatile("cp.async.wait_group 1;" ::: "memory");
        } else {
            asm volatile("cp.async.wait_group 0;" ::: "memory");
        }
        __syncthreads();
        const float* S  = sf + (kc & 1) * STG_F;
        const float* Ah = S, *At = S + 4608, *Bw = S + 9216, *Be = S + 11520;

#pragma unroll
        for (int ks = 0; ks < 4; ks++) {
            uint32_t bw[4][2], be[4][2];
#pragma unroll
            for (int ns = 0; ns < 4; ns++) {
                int col = warpn * 32 + ns * 8 + (lane >> 2);
                int r0  = ks * 8 + (lane & 3);
                bw[ns][0] = __float_as_uint(Bw[r0 * 72 + col]);
                bw[ns][1] = __float_as_uint(Bw[(r0 + 4) * 72 + col]);
                be[ns][0] = __float_as_uint(Be[r0 * 72 + col]);
                be[ns][1] = __float_as_uint(Be[(r0 + 4) * 72 + col]);
            }
#pragma unroll
            for (int ms = 0; ms < 4; ms++) {
                int row = warpm * 64 + ms * 16 + (lane >> 2);
                int c0  = ks * 8 + (lane & 3);
                uint32_t ah[4], at[4];
                ah[0] = __float_as_uint(Ah[row * 36 + c0]);
                ah[1] = __float_as_uint(Ah[(row + 8) * 36 + c0]);
                ah[2] = __float_as_uint(Ah[row * 36 + c0 + 4]);
                ah[3] = __float_as_uint(Ah[(row + 8) * 36 + c0 + 4]);
                at[0] = __float_as_uint(At[row * 36 + c0]);
                at[1] = __float_as_uint(At[(row + 8) * 36 + c0]);
                at[2] = __float_as_uint(At[row * 36 + c0 + 4]);
                at[3] = __float_as_uint(At[(row + 8) * 36 + c0 + 4]);
#pragma unroll
                for (int ns = 0; ns < 4; ns++) {
                    mma_tf32(accz[ms][ns], ah, bw[ns]);
                    mma_tf32(acca[ms][ns], at, be[ns]);
                }
            }
        }
        __syncthreads();
    }

    // ---- epilogue: tanh, h2 out, divergence partials ----
    float dv[4][2];
#pragma unroll
    for (int ms = 0; ms < 4; ms++) { dv[ms][0] = 0.f; dv[ms][1] = 0.f; }

#pragma unroll
    for (int ms = 0; ms < 4; ms++)
#pragma unroll
        for (int ns = 0; ns < 4; ns++)
#pragma unroll
            for (int c = 0; c < 4; c++) {
                int row = stile * 128 + warpm * 64 + ms * 16 + (lane >> 2) + ((c >> 1) ? 8 : 0);
                int col = ntile * 64 + warpn * 32 + ns * 8 + 2 * (lane & 3) + (c & 1);
                float h2 = tanhf(accz[ms][ns][c] + b2[col]);
                g_h2[(size_t)row * H_ + col] = h2;
                dv[ms][c >> 1] = fmaf(acca[ms][ns][c], fmaf(h2, h2, -1.f), dv[ms][c >> 1]);
            }
#pragma unroll
    for (int ms = 0; ms < 4; ms++)
#pragma unroll
        for (int h = 0; h < 2; h++) {
            float v = dv[ms][h];
            v += __shfl_xor_sync(0xffffffffu, v, 1);
            v += __shfl_xor_sync(0xffffffffu, v, 2);
            if ((lane & 3) == 0) {
                int s = stile * 128 + warpm * 64 + ms * 16 + (lane >> 2) + h * 8;
                g_divp[(ntile * 2 + warpn) * B_ + s] = v;
            }
        }
}

// ---------------------------------------------------------------------------
// Kernel 4: phase 3 v3 — out[s][m] = (h2[s][:]@W3[:][m]+b3)/2 + div column.
//   grid 128 (16 samples each), 256 threads.
//   Thread = (sg 0..3, cg 0..15, ks 0..3): samples sg*4..+3, cols cg*4..+3,
//   K-split ks covers kk in [ks*32, ks*32+32) of each 128-K chunk.
//   Smem: h2t[kk][s] transposed (LDS.128 over 4 samples), w3s[kk][m].
//   Inner iter: 2x LDS.128 + 16 FMA. Split-K reduced via smem at the end.
// ---------------------------------------------------------------------------
#define P3_BM 16
#define P3_KC 128
__global__ __launch_bounds__(256) void phase3_kernel(
    const float* __restrict__ W3, const float* __restrict__ b3,
    float* __restrict__ out)
{
    __shared__ float h2t[P3_KC][P3_BM];        // [kk][s], 8 KB
    __shared__ float w3s[P3_KC][D_ + 4];       // [kk][m], 34.8 KB (also scratch)

    const int tid = threadIdx.x;
    const int sg  = tid & 3;
    const int cg  = (tid >> 2) & 15;
    const int ks  = tid >> 6;
    const int s0  = blockIdx.x * P3_BM;

    float acc[4][4];
#pragma unroll
    for (int si = 0; si < 4; si++)
#pragma unroll
        for (int ci = 0; ci < 4; ci++) acc[si][ci] = 0.f;

    for (int c = 0; c < H_ / P3_KC; c++) {
        const int kb = c * P3_KC;
        // stage h2 transposed: 16 samples x 128 k = 512 float4, 2/thread
#pragma unroll
        for (int i = 0; i < 2; i++) {
            int idx = i * 256 + tid;            // 0..511
            int s = idx & 15, q = idx >> 4;     // q 0..31
            float4 v = *(const float4*)(g_h2 + (size_t)(s0 + s) * H_ + kb + q * 4);
            h2t[q * 4 + 0][s] = v.x;
            h2t[q * 4 + 1][s] = v.y;
            h2t[q * 4 + 2][s] = v.z;
            h2t[q * 4 + 3][s] = v.w;
        }
        // stage W3: 128 k x 64 m = 2048 float4, 8/thread
#pragma unroll
        for (int i = 0; i < 8; i++) {
            int idx = i * 256 + tid;            // 0..2047
            int kk = idx >> 4, q = idx & 15;
            *(float4*)&w3s[kk][q * 4] =
                *(const float4*)(W3 + (size_t)(kb + kk) * D_ + q * 4);
        }
        __syncthreads();

        const int kklo = ks * 32;
#pragma unroll 8
        for (int k2 = 0; k2 < 32; k2++) {
            int kk = kklo + k2;
            float4 h = *(const float4*)&h2t[kk][sg * 4];
            float4 w = *(const float4*)&w3s[kk][cg * 4];
            float hv[4] = {h.x, h.y, h.z, h.w};
            float wv[4] = {w.x, w.y, w.z, w.w};
#pragma unroll
            for (int si = 0; si < 4; si++)
#pragma unroll
                for (int ci = 0; ci < 4; ci++)
                    acc[si][ci] = fmaf(hv[si], wv[ci], acc[si][ci]);
        }
        __syncthreads();
    }

    // ---- split-K reduction through smem (reuse w3s as scratch) ----
    {
        float* scr = &w3s[0][0];               // 4*64*17 = 4352 <= 8704 floats
        const int t64 = tid & 63;
#pragma unroll
        for (int si = 0; si < 4; si++)
#pragma unroll
            for (int ci = 0; ci < 4; ci++)
                scr[(ks * 64 + t64) * 17 + si * 4 + ci] = acc[si][ci];
        __syncthreads();
        if (ks == 0) {
#pragma unroll
            for (int si = 0; si < 4; si++)
#pragma unroll
                for (int ci = 0; ci < 4; ci++) {
                    float v = acc[si][ci];
#pragma unroll
                    for (int p = 1; p < 4; p++)
                        v += scr[(p * 64 + t64) * 17 + si * 4 + ci];
                    acc[si][ci] = v;
                }
            // write outputs
#pragma unroll
            for (int si = 0; si < 4; si++) {
                int s = s0 + sg * 4 + si;
                float* op = out + (size_t)s * 65 + cg * 4;
#pragma unroll
                for (int ci = 0; ci < 4; ci++)
                    op[ci] = 0.5f * (acc[si][ci] + b3[cg * 4 + ci]);
            }
        }
    }
    // ---- divergence column ----
    if (tid < P3_BM) {
        int s = s0 + tid;
        float d = 0.f;
#pragma unroll
        for (int p = 0; p < 16; p++) d += g_divp[p * B_ + s];
        out[(size_t)s * 65 + D_] = 0.5f * d;
    }
}

// ---------------------------------------------------------------------------
extern "C" void kernel_launch(void* const* d_in, const int* in_sizes, int n_in,
                              void* d_out, int out_size) {
    const float* t  = (const float*)d_in[0];
    const float* x  = (const float*)d_in[1];
    const float* W1 = (const float*)d_in[2];
    const float* b1 = (const float*)d_in[3];
    const float* W2 = (const float*)d_in[4];
    const float* b2 = (const float*)d_in[5];
    const float* W3 = (const float*)d_in[6];
    const float* b3 = (const float*)d_in[7];
    float* out = (float*)d_out;

    const int prep_smem = (512 * 65 + 8 * 64) * 4;
    const int gemm_smem = 2 * STG_F * 4;     // 110592 B
    cudaFuncSetAttribute(prep_kernel,  cudaFuncAttributeMaxDynamicSharedMemorySize, prep_smem);
    cudaFuncSetAttribute(gemm2_kernel, cudaFuncAttributeMaxDynamicSharedMemorySize, gemm_smem);

    prep_kernel<<<64, 512, prep_smem>>>(W1, W2, W3);
    phase1_kernel<<<B_ / 16, 512>>>(t, x, W1, b1);
    gemm2_kernel<<<dim3(B_ / 128, H_ / 64), 128, gemm_smem>>>(b2);
    phase3_kernel<<<B_ / P3_BM, 256>>>(W3, b3, out);
}

// round 14
// speedup vs baseline: 3.0142x; 1.1244x over previous
#include <cuda_runtime.h>
#include <math.h>
#include <stdint.h>

#define B_  2048
#define D_  64
#define H_  512

// ---------------- intermediates (no allocation allowed) ----------------
__device__ __align__(256) float g_W2r[H_ * H_];      // rtf32(W2[j][k])
__device__ __align__(256) float g_Er [H_ * H_];      // rtf32(E[j][k])
__device__ __align__(256) float g_h1 [B_ * H_];      // rtf32(h1[s][j])
__device__ __align__(256) float g_t1 [B_ * H_];      // rtf32(h1^2-1)
__device__ __align__(256) float g_outp[8 * B_ * D_]; // per-ntile out partials
__device__ __align__(256) float g_divp[16 * B_];     // div partials

// ---------------- helpers ----------------
__device__ __forceinline__ uint32_t smem_u32(const void* p) {
    uint32_t a;
    asm("{ .reg .u64 t; cvta.to.shared.u64 t, %1; cvt.u32.u64 %0, t; }"
        : "=r"(a) : "l"(p));
    return a;
}
__device__ __forceinline__ float rtf32(float v) {
    uint32_t r;
    asm("cvt.rna.tf32.f32 %0, %1;" : "=r"(r) : "f"(v));
    return __uint_as_float(r);
}
__device__ __forceinline__ void mma_tf32(float* d, const uint32_t* a, const uint32_t* b) {
    asm volatile(
        "mma.sync.aligned.m16n8k8.row.col.f32.tf32.tf32.f32 "
        "{%0,%1,%2,%3}, {%4,%5,%6,%7}, {%8,%9}, {%0,%1,%2,%3};"
        : "+f"(d[0]), "+f"(d[1]), "+f"(d[2]), "+f"(d[3])
        : "r"(a[0]), "r"(a[1]), "r"(a[2]), "r"(a[3]), "r"(b[0]), "r"(b[1]));
}
#define CP_ASYNC16(dst, src) \
    asm volatile("cp.async.ca.shared.global [%0], [%1], 16;" :: "r"(dst), "l"(src))
#define CP_COMMIT() asm volatile("cp.async.commit_group;" ::: "memory")

// ---------------------------------------------------------------------------
// Kernel 1: fused prep + phase1 (independent work, one launch).
//   blocks 0..63:   prep — g_Er[j][k] = rtf32(W2[j][k]*sum_m W1[m][j]W3[k][m]),
//                   g_W2r[j][k] = rtf32(W2[j][k]). 8 j's per block, thread = k.
//   blocks 64..191: phase1 — h1/t1 for 16 samples per block.
// ---------------------------------------------------------------------------
__global__ __launch_bounds__(512) void pre_kernel(
    const float* __restrict__ t,  const float* __restrict__ x,
    const float* __restrict__ W1, const float* __restrict__ b1,
    const float* __restrict__ W2, const float* __restrict__ W3)
{
    __shared__ float sbuf[65 * 16];
    const int tid = threadIdx.x;

    if (blockIdx.x < 64) {
        // ---- prep ----
        float* w1s = sbuf;                     // [8][64]
        const int jb = blockIdx.x * 8;
        for (int idx = tid; idx < 8 * D_; idx += 512) {
            int jj = idx >> 6, m = idx & 63;
            w1s[jj * 64 + m] = W1[m * H_ + jb + jj];
        }
        __syncthreads();

        const int k = tid;
        float r[D_];
        const float4* w3r = (const float4*)(W3 + (size_t)k * D_);
#pragma unroll
        for (int q = 0; q < D_ / 4; q++) {
            float4 v = w3r[q];
            r[4*q+0] = v.x; r[4*q+1] = v.y; r[4*q+2] = v.z; r[4*q+3] = v.w;
        }
        float acc[8] = {0,0,0,0,0,0,0,0};
#pragma unroll 8
        for (int m = 0; m < D_; m++) {
            float w3v = r[m];
#pragma unroll
            for (int jj = 0; jj < 8; jj++)
                acc[jj] = fmaf(w1s[jj * 64 + m], w3v, acc[jj]);
        }
#pragma unroll
        for (int jj = 0; jj < 8; jj++) {
            int j = jb + jj;
            float w2 = W2[j * H_ + k];
            g_Er [j * H_ + k] = rtf32(w2 * acc[jj]);
            g_W2r[j * H_ + k] = rtf32(w2);
        }
    } else {
        // ---- phase1 ----
        float* xs = sbuf;                      // [65][16]
        const int s0 = (blockIdx.x - 64) * 16;
        for (int idx = tid; idx < 65 * 16; idx += 512) {
            int i = idx >> 4, s = idx & 15;
            xs[i * 16 + s] = (i < D_) ? x[(size_t)(s0 + s) * 65 + i] : t[0];
        }
        __syncthreads();

        const int j = tid;
        float acc[16];
#pragma unroll
        for (int s = 0; s < 16; s++) acc[s] = 0.f;
#pragma unroll 5
        for (int i = 0; i < 65; i++) {
            float w = W1[i * H_ + j];
#pragma unroll
            for (int s = 0; s < 16; s++) acc[s] = fmaf(xs[i * 16 + s], w, acc[s]);
        }
        float bj = b1[j];
#pragma unroll
        for (int s = 0; s < 16; s++) {
            float h = tanhf(acc[s] + bj);
            g_h1[(size_t)(s0 + s) * H_ + j] = rtf32(h);
            g_t1[(size_t)(s0 + s) * H_ + j] = rtf32(fmaf(h, h, -1.f));
        }
    }
}

// ---------------------------------------------------------------------------
// Kernel 2: tf32 mma.sync double-GEMM + fused W3-partial epilogue.
//   grid (16 stiles, 8 ntiles), 128 thr = 4 warps (2m x 2n), warp tile 64x32.
//   Mainloop: z = h1 @ W2, a = t1 @ E; K chunks of 32, cp.async 2-stage.
//   Epilogue: h2 = tanh(z+b2) -> smem (tf32); div partials -> g_divp;
//             then po = h2tile(128x64k) @ W3[ntile k-slice][64m] via 8 more
//             mma k-steps -> g_outp[ntile][s][m]  (each elem written once).
// Smem/stage: Ah[128*36] At[128*36] Bw[32*72] Be[32*72] = 13824 floats.
// Epilogue reuses stage 0: h2s[128*68] + w3s[64*68] = 13056 floats.
// ---------------------------------------------------------------------------
#define STG_F 13824
__global__ __launch_bounds__(128, 1) void gemm2_kernel(
    const float* __restrict__ b2, const float* __restrict__ W3)
{
    extern __shared__ float sf[];
    const int tid  = threadIdx.x;
    const int lane = tid & 31, wid = tid >> 5;
    const int warpm = wid >> 1, warpn = wid & 1;
    const int stile = blockIdx.x, ntile = blockIdx.y;

    auto issue_chunk = [&](int kc, int st) {
        uint32_t sbase = smem_u32(sf + st * STG_F);
#pragma unroll
        for (int mm = 0; mm < 2; mm++) {
            const float* s = (mm ? g_t1 : g_h1) + (size_t)(stile * 128) * H_ + kc * 32;
            uint32_t d = sbase + mm * 4608 * 4;
#pragma unroll
            for (int i = 0; i < 8; i++) {
                int idx = i * 128 + tid;
                int row = idx >> 3, qc = idx & 7;
                CP_ASYNC16(d + (row * 36 + qc * 4) * 4, s + (size_t)row * H_ + qc * 4);
            }
        }
#pragma unroll
        for (int mm = 0; mm < 2; mm++) {
            const float* s = (mm ? g_Er : g_W2r) + (size_t)(kc * 32) * H_ + ntile * 64;
            uint32_t d = sbase + (9216 + mm * 2304) * 4;
#pragma unroll
            for (int i = 0; i < 4; i++) {
                int idx = i * 128 + tid;
                int row = idx >> 4, qc = idx & 15;
                CP_ASYNC16(d + (row * 72 + qc * 4) * 4, s + (size_t)row * H_ + qc * 4);
            }
        }
        CP_COMMIT();
    };

    float accz[4][4][4], acca[4][4][4];
#pragma unroll
    for (int ms = 0; ms < 4; ms++)
#pragma unroll
        for (int ns = 0; ns < 4; ns++)
#pragma unroll
            for (int c = 0; c < 4; c++) { accz[ms][ns][c] = 0.f; acca[ms][ns][c] = 0.f; }

    issue_chunk(0, 0);
    for (int kc = 0; kc < 16; kc++) {
        if (kc < 15) {
            issue_chunk(kc + 1, (kc + 1) & 1);
            asm volatile("cp.async.wait_group 1;" ::: "memory");
        } else {
            asm volatile("cp.async.wait_group 0;" ::: "memory");
        }
        __syncthreads();
        const float* S  = sf + (kc & 1) * STG_F;
        const float* Ah = S, *At = S + 4608, *Bw = S + 9216, *Be = S + 11520;

#pragma unroll
        for (int ks = 0; ks < 4; ks++) {
            uint32_t bw[4][2], be[4][2];
#pragma unroll
            for (int ns = 0; ns < 4; ns++) {
                int col = warpn * 32 + ns * 8 + (lane >> 2);
                int r0  = ks * 8 + (lane & 3);
                bw[ns][0] = __float_as_uint(Bw[r0 * 72 + col]);
                bw[ns][1] = __float_as_uint(Bw[(r0 + 4) * 72 + col]);
                be[ns][0] = __float_as_uint(Be[r0 * 72 + col]);
                be[ns][1] = __float_as_uint(Be[(r0 + 4) * 72 + col]);
            }
#pragma unroll
            for (int ms = 0; ms < 4; ms++) {
                int row = warpm * 64 + ms * 16 + (lane >> 2);
                int c0  = ks * 8 + (lane & 3);
                uint32_t ah[4], at[4];
                ah[0] = __float_as_uint(Ah[row * 36 + c0]);
                ah[1] = __float_as_uint(Ah[(row + 8) * 36 + c0]);
                ah[2] = __float_as_uint(Ah[row * 36 + c0 + 4]);
                ah[3] = __float_as_uint(Ah[(row + 8) * 36 + c0 + 4]);
                at[0] = __float_as_uint(At[row * 36 + c0]);
                at[1] = __float_as_uint(At[(row + 8) * 36 + c0]);
                at[2] = __float_as_uint(At[row * 36 + c0 + 4]);
                at[3] = __float_as_uint(At[(row + 8) * 36 + c0 + 4]);
#pragma unroll
                for (int ns = 0; ns < 4; ns++) {
                    mma_tf32(accz[ms][ns], ah, bw[ns]);
                    mma_tf32(acca[ms][ns], at, be[ns]);
                }
            }
        }
        __syncthreads();
    }

    // ---- epilogue: tanh, h2 -> smem (tf32), divergence partials ----
    float* h2s = sf;                 // [128][68]
    float* w3s = sf + 128 * 68;      // [64][68]

    // stage W3 k-slice (rows ntile*64 .. +63), tf32-rounded
#pragma unroll
    for (int i = 0; i < 8; i++) {
        int idx = i * 128 + tid;                 // 0..1023
        int row = idx >> 4, q = idx & 15;
        float4 v = *(const float4*)(W3 + (size_t)(ntile * 64 + row) * D_ + q * 4);
        float* d = &w3s[row * 68 + q * 4];
        d[0] = rtf32(v.x); d[1] = rtf32(v.y); d[2] = rtf32(v.z); d[3] = rtf32(v.w);
    }

    float dv[4][2];
#pragma unroll
    for (int ms = 0; ms < 4; ms++) { dv[ms][0] = 0.f; dv[ms][1] = 0.f; }

#pragma unroll
    for (int ms = 0; ms < 4; ms++)
#pragma unroll
        for (int ns = 0; ns < 4; ns++) {
            int rl = warpm * 64 + ms * 16 + (lane >> 2);
            int cl = warpn * 32 + ns * 8 + 2 * (lane & 3);
            float b20 = b2[ntile * 64 + cl], b21 = b2[ntile * 64 + cl + 1];
            float h0 = tanhf(accz[ms][ns][0] + b20);
            float h1v = tanhf(accz[ms][ns][1] + b21);
            float h2v = tanhf(accz[ms][ns][2] + b20);
            float h3 = tanhf(accz[ms][ns][3] + b21);
            dv[ms][0] = fmaf(acca[ms][ns][0], fmaf(h0, h0, -1.f), dv[ms][0]);
            dv[ms][0] = fmaf(acca[ms][ns][1], fmaf(h1v, h1v, -1.f), dv[ms][0]);
            dv[ms][1] = fmaf(acca[ms][ns][2], fmaf(h2v, h2v, -1.f), dv[ms][1]);
            dv[ms][1] = fmaf(acca[ms][ns][3], fmaf(h3, h3, -1.f), dv[ms][1]);
            float2 lo = make_float2(rtf32(h0), rtf32(h1v));
            float2 hi = make_float2(rtf32(h2v), rtf32(h3));
            *(float2*)&h2s[rl * 68 + cl]       = lo;
            *(float2*)&h2s[(rl + 8) * 68 + cl] = hi;
        }
#pragma unroll
    for (int ms = 0; ms < 4; ms++)
#pragma unroll
        for (int h = 0; h < 2; h++) {
            float v = dv[ms][h];
            v += __shfl_xor_sync(0xffffffffu, v, 1);
            v += __shfl_xor_sync(0xffffffffu, v, 2);
            if ((lane & 3) == 0) {
                int s = stile * 128 + warpm * 64 + ms * 16 + (lane >> 2) + h * 8;
                g_divp[(ntile * 2 + warpn) * B_ + s] = v;
            }
        }
    __syncthreads();

    // ---- partial out GEMM: po = h2s(128 x 64k) @ w3s(64k x 64m) ----
    float accp[4][4][4];
#pragma unroll
    for (int ms = 0; ms < 4; ms++)
#pragma unroll
        for (int ns = 0; ns < 4; ns++)
#pragma unroll
            for (int c = 0; c < 4; c++) accp[ms][ns][c] = 0.f;

#pragma unroll
    for (int ksp = 0; ksp < 8; ksp++) {
        uint32_t bf[4][2];
#pragma unroll
        for (int ns = 0; ns < 4; ns++) {
            int col = warpn * 32 + ns * 8 + (lane >> 2);
            int r0  = ksp * 8 + (lane & 3);
            bf[ns][0] = __float_as_uint(w3s[r0 * 68 + col]);
            bf[ns][1] = __float_as_uint(w3s[(r0 + 4) * 68 + col]);
        }
#pragma unroll
        for (int ms = 0; ms < 4; ms++) {
            int row = warpm * 64 + ms * 16 + (lane >> 2);
            int c0  = ksp * 8 + (lane & 3);
            uint32_t af[4];
            af[0] = __float_as_uint(h2s[row * 68 + c0]);
            af[1] = __float_as_uint(h2s[(row + 8) * 68 + c0]);
            af[2] = __float_as_uint(h2s[row * 68 + c0 + 4]);
            af[3] = __float_as_uint(h2s[(row + 8) * 68 + c0 + 4]);
#pragma unroll
            for (int ns = 0; ns < 4; ns++)
                mma_tf32(accp[ms][ns], af, bf[ns]);
        }
    }

    // store partials: g_outp[ntile][s][m], each element written exactly once
#pragma unroll
    for (int ms = 0; ms < 4; ms++)
#pragma unroll
        for (int ns = 0; ns < 4; ns++) {
            int rg = stile * 128 + warpm * 64 + ms * 16 + (lane >> 2);
            int cl = warpn * 32 + ns * 8 + 2 * (lane & 3);
            *(float2*)&g_outp[(size_t)(ntile * B_ + rg) * 64 + cl] =
                make_float2(accp[ms][ns][0], accp[ms][ns][1]);
            *(float2*)&g_outp[(size_t)(ntile * B_ + rg + 8) * 64 + cl] =
                make_float2(accp[ms][ns][2], accp[ms][ns][3]);
        }
}

// ---------------------------------------------------------------------------
// Kernel 3: reduce — out[s][m] = 0.5*(sum_nt outp[nt][s][m] + b3[m]);
//           out[s][64] = 0.5*sum_p divp[p][s].  64 blocks x 512 thr.
// ---------------------------------------------------------------------------
__global__ __launch_bounds__(512) void reduce_kernel(
    const float* __restrict__ b3, float* __restrict__ out)
{
    const int tid = threadIdx.x;
    const int m  = tid & 63;
    const int sl = tid >> 6;               // 0..7
    const int sb = blockIdx.x * 32;
    const float bm = b3[m];

#pragma unroll
    for (int i = 0; i < 4; i++) {
        int s = sb + sl * 4 + i;
        float acc = 0.f;
#pragma unroll
        for (int nt = 0; nt < 8; nt++)
            acc += g_outp[(size_t)(nt * B_ + s) * 64 + m];
        out[(size_t)s * 65 + m] = 0.5f * (acc + bm);
    }
    if (tid < 32) {
        int s = sb + tid;
        float d = 0.f;
#pragma unroll
        for (int p = 0; p < 16; p++) d += g_divp[p * B_ + s];
        out[(size_t)s * 65 + D_] = 0.5f * d;
    }
}

// ---------------------------------------------------------------------------
extern "C" void kernel_launch(void* const* d_in, const int* in_sizes, int n_in,
                              void* d_out, int out_size) {
    const float* t  = (const float*)d_in[0];
    const float* x  = (const float*)d_in[1];
    const float* W1 = (const float*)d_in[2];
    const float* b1 = (const float*)d_in[3];
    const float* W2 = (const float*)d_in[4];
    const float* b2 = (const float*)d_in[5];
    const float* W3 = (const float*)d_in[6];
    const float* b3 = (const float*)d_in[7];
    float* out = (float*)d_out;

    const int gemm_smem = 2 * STG_F * 4;     // 110592 B
    cudaFuncSetAttribute(gemm2_kernel, cudaFuncAttributeMaxDynamicSharedMemorySize, gemm_smem);

    pre_kernel<<<192, 512>>>(t, x, W1, b1, W2, W3);
    gemm2_kernel<<<dim3(B_ / 128, H_ / 64), 128, gemm_smem>>>(b2, W3);
    reduce_kernel<<<64, 512>>>(b3, out);
}

// round 16
// speedup vs baseline: 3.1418x; 1.0423x over previous
#include <cuda_runtime.h>
#include <math.h>
#include <stdint.h>

#define B_  2048
#define D_  64
#define H_  512

// ---------------- intermediates (no allocation allowed) ----------------
__device__ __align__(256) float g_W2r[H_ * H_];      // rtf32(W2[j][k])
__device__ __align__(256) float g_Er [H_ * H_];      // rtf32(E[j][k])
__device__ __align__(256) float g_h1 [B_ * H_];      // rtf32(h1[s][j])
__device__ __align__(256) float g_t1 [B_ * H_];      // rtf32(h1^2-1)
__device__ __align__(256) float g_outp[8 * B_ * D_]; // per-ntile out partials
__device__ __align__(256) float g_divp[16 * B_];     // div partials

// ---------------- helpers ----------------
__device__ __forceinline__ uint32_t smem_u32(const void* p) {
    uint32_t a;
    asm("{ .reg .u64 t; cvta.to.shared.u64 t, %1; cvt.u32.u64 %0, t; }"
        : "=r"(a) : "l"(p));
    return a;
}
__device__ __forceinline__ float rtf32(float v) {
    uint32_t r;
    asm("cvt.rna.tf32.f32 %0, %1;" : "=r"(r) : "f"(v));
    return __uint_as_float(r);
}
__device__ __forceinline__ void mma_tf32(float* d, const uint32_t* a, const uint32_t* b) {
    asm volatile(
        "mma.sync.aligned.m16n8k8.row.col.f32.tf32.tf32.f32 "
        "{%0,%1,%2,%3}, {%4,%5,%6,%7}, {%8,%9}, {%0,%1,%2,%3};"
        : "+f"(d[0]), "+f"(d[1]), "+f"(d[2]), "+f"(d[3])
        : "r"(a[0]), "r"(a[1]), "r"(a[2]), "r"(a[3]), "r"(b[0]), "r"(b[1]));
}
#define CP_ASYNC16(dst, src) \
    asm volatile("cp.async.ca.shared.global [%0], [%1], 16;" :: "r"(dst), "l"(src))
#define CP_COMMIT() asm volatile("cp.async.commit_group;" ::: "memory")

// ---------------------------------------------------------------------------
// Kernel 1: prep — g_Er[j][k] = rtf32(W2[j][k]*sum_m W1[m][j]W3[k][m]),
//           g_W2r[j][k] = rtf32(W2[j][k]).  grid 64, block 512 (thread = k).
//   W3 staged in dynamic smem (133 KB) — keeps register count low, no spills.
// ---------------------------------------------------------------------------
__global__ __launch_bounds__(512) void prep_kernel(
    const float* __restrict__ W1, const float* __restrict__ W2,
    const float* __restrict__ W3)
{
    extern __shared__ float ps[];          // w3s[512*65] | w1s[8*64]
    float* w3s = ps;
    float* w1s = ps + 512 * 65;
    const int tid = threadIdx.x;
    const int jb  = blockIdx.x * 8;

    for (int idx = tid; idx < H_ * D_; idx += 512) {
        int k = idx >> 6, m = idx & 63;
        w3s[k * 65 + m] = W3[idx];
    }
    for (int idx = tid; idx < 8 * D_; idx += 512) {
        int jj = idx >> 6, m = idx & 63;
        w1s[jj * 64 + m] = W1[m * H_ + jb + jj];
    }
    __syncthreads();

    const int k = tid;
    float acc[8] = {0,0,0,0,0,0,0,0};
#pragma unroll 8
    for (int m = 0; m < D_; m++) {
        float w3v = w3s[k * 65 + m];
#pragma unroll
        for (int jj = 0; jj < 8; jj++) acc[jj] = fmaf(w1s[jj * 64 + m], w3v, acc[jj]);
    }
#pragma unroll
    for (int jj = 0; jj < 8; jj++) {
        int j = jb + jj;
        float w2 = W2[j * H_ + k];
        g_Er [j * H_ + k] = rtf32(w2 * acc[jj]);
        g_W2r[j * H_ + k] = rtf32(w2);
    }
}

// ---------------------------------------------------------------------------
// Kernel 2: phase 1 — h1/t1 for 16 samples per block. 128 blocks x 512 thr.
// ---------------------------------------------------------------------------
__global__ __launch_bounds__(512) void phase1_kernel(
    const float* __restrict__ t, const float* __restrict__ x,
    const float* __restrict__ W1, const float* __restrict__ b1)
{
    __shared__ float xs[65][16];
    const int tid = threadIdx.x;
    const int s0  = blockIdx.x * 16;

    for (int idx = tid; idx < 65 * 16; idx += 512) {
        int i = idx >> 4, s = idx & 15;
        xs[i][s] = (i < D_) ? x[(size_t)(s0 + s) * 65 + i] : t[0];
    }
    __syncthreads();

    const int j = tid;
    float acc[16];
#pragma unroll
    for (int s = 0; s < 16; s++) acc[s] = 0.f;
#pragma unroll 5
    for (int i = 0; i < 65; i++) {
        float w = W1[i * H_ + j];
#pragma unroll
        for (int s = 0; s < 16; s++) acc[s] = fmaf(xs[i][s], w, acc[s]);
    }
    float bj = b1[j];
#pragma unroll
    for (int s = 0; s < 16; s++) {
        float h = tanhf(acc[s] + bj);
        g_h1[(size_t)(s0 + s) * H_ + j] = rtf32(h);
        g_t1[(size_t)(s0 + s) * H_ + j] = rtf32(fmaf(h, h, -1.f));
    }
}

// ---------------------------------------------------------------------------
// Kernel 3: tf32 mma.sync double-GEMM + fused W3-partial epilogue.
//   grid (16 stiles, 8 ntiles), 128 thr = 4 warps (2m x 2n), warp tile 64x32.
//   Mainloop: z = h1 @ W2, a = t1 @ E; K chunks of 32, cp.async 2-stage.
//   Epilogue: h2 = tanh(z+b2) -> smem (tf32); div partials -> g_divp;
//             then po = h2tile(128x64k) @ W3[ntile k-slice][64m] via 8 more
//             mma k-steps -> g_outp[ntile][s][m]  (each elem written once).
// Smem/stage: Ah[128*36] At[128*36] Bw[32*72] Be[32*72] = 13824 floats.
// Epilogue reuses stage 0: h2s[128*68] + w3s[64*68] = 13056 floats.
// ---------------------------------------------------------------------------
#define STG_F 13824
__global__ __launch_bounds__(128, 1) void gemm2_kernel(
    const float* __restrict__ b2, const float* __restrict__ W3)
{
    extern __shared__ float sf[];
    const int tid  = threadIdx.x;
    const int lane = tid & 31, wid = tid >> 5;
    const int warpm = wid >> 1, warpn = wid & 1;
    const int stile = blockIdx.x, ntile = blockIdx.y;

    auto issue_chunk = [&](int kc, int st) {
        uint32_t sbase = smem_u32(sf + st * STG_F);
#pragma unroll
        for (int mm = 0; mm < 2; mm++) {
            const float* s = (mm ? g_t1 : g_h1) + (size_t)(stile * 128) * H_ + kc * 32;
            uint32_t d = sbase + mm * 4608 * 4;
#pragma unroll
            for (int i = 0; i < 8; i++) {
                int idx = i * 128 + tid;
                int row = idx >> 3, qc = idx & 7;
                CP_ASYNC16(d + (row * 36 + qc * 4) * 4, s + (size_t)row * H_ + qc * 4);
            }
        }
#pragma unroll
        for (int mm = 0; mm < 2; mm++) {
            const float* s = (mm ? g_Er : g_W2r) + (size_t)(kc * 32) * H_ + ntile * 64;
            uint32_t d = sbase + (9216 + mm * 2304) * 4;
#pragma unroll
            for (int i = 0; i < 4; i++) {
                int idx = i * 128 + tid;
                int row = idx >> 4, qc = idx & 15;
                CP_ASYNC16(d + (row * 72 + qc * 4) * 4, s + (size_t)row * H_ + qc * 4);
            }
        }
        CP_COMMIT();
    };

    float accz[4][4][4], acca[4][4][4];
#pragma unroll
    for (int ms = 0; ms < 4; ms++)
#pragma unroll
        for (int ns = 0; ns < 4; ns++)
#pragma unroll
            for (int c = 0; c < 4; c++) { accz[ms][ns][c] = 0.f; acca[ms][ns][c] = 0.f; }

    issue_chunk(0, 0);
    for (int kc = 0; kc < 16; kc++) {
        if (kc < 15) {
            issue_chunk(kc + 1, (kc + 1) & 1);
            asm volatile("cp.async.wait_group 1;" ::: "memory");
        } else {
            asm volatile("cp.async.wait_group 0;" ::: "memory");
        }
        __syncthreads();
        const float* S  = sf + (kc & 1) * STG_F;
        const float* Ah = S, *At = S + 4608, *Bw = S + 9216, *Be = S + 11520;

#pragma unroll
        for (int ks = 0; ks < 4; ks++) {
            uint32_t bw[4][2], be[4][2];
#pragma unroll
            for (int ns = 0; ns < 4; ns++) {
                int col = warpn * 32 + ns * 8 + (lane >> 2);
                int r0  = ks * 8 + (lane & 3);
                bw[ns][0] = __float_as_uint(Bw[r0 * 72 + col]);
                bw[ns][1] = __float_as_uint(Bw[(r0 + 4) * 72 + col]);
                be[ns][0] = __float_as_uint(Be[r0 * 72 + col]);
                be[ns][1] = __float_as_uint(Be[(r0 + 4) * 72 + col]);
            }
#pragma unroll
            for (int ms = 0; ms < 4; ms++) {
                int row = warpm * 64 + ms * 16 + (lane >> 2);
                int c0  = ks * 8 + (lane & 3);
                uint32_t ah[4], at[4];
                ah[0] = __float_as_uint(Ah[row * 36 + c0]);
                ah[1] = __float_as_uint(Ah[(row + 8) * 36 + c0]);
                ah[2] = __float_as_uint(Ah[row * 36 + c0 + 4]);
                ah[3] = __float_as_uint(Ah[(row + 8) * 36 + c0 + 4]);
                at[0] = __float_as_uint(At[row * 36 + c0]);
                at[1] = __float_as_uint(At[(row + 8) * 36 + c0]);
                at[2] = __float_as_uint(At[row * 36 + c0 + 4]);
                at[3] = __float_as_uint(At[(row + 8) * 36 + c0 + 4]);
#pragma unroll
                for (int ns = 0; ns < 4; ns++) {
                    mma_tf32(accz[ms][ns], ah, bw[ns]);
                    mma_tf32(acca[ms][ns], at, be[ns]);
                }
            }
        }
        __syncthreads();
    }

    // ---- epilogue: tanh, h2 -> smem (tf32), divergence partials ----
    float* h2s = sf;                 // [128][68]
    float* w3s = sf + 128 * 68;      // [64][68]

    // stage W3 k-slice (rows ntile*64 .. +63), tf32-rounded
#pragma unroll
    for (int i = 0; i < 8; i++) {
        int idx = i * 128 + tid;                 // 0..1023
        int row = idx >> 4, q = idx & 15;
        float4 v = *(const float4*)(W3 + (size_t)(ntile * 64 + row) * D_ + q * 4);
        float* d = &w3s[row * 68 + q * 4];
        d[0] = rtf32(v.x); d[1] = rtf32(v.y); d[2] = rtf32(v.z); d[3] = rtf32(v.w);
    }

    float dv[4][2];
#pragma unroll
    for (int ms = 0; ms < 4; ms++) { dv[ms][0] = 0.f; dv[ms][1] = 0.f; }

#pragma unroll
    for (int ms = 0; ms < 4; ms++)
#pragma unroll
        for (int ns = 0; ns < 4; ns++) {
            int rl = warpm * 64 + ms * 16 + (lane >> 2);
            int cl = warpn * 32 + ns * 8 + 2 * (lane & 3);
            float b20 = b2[ntile * 64 + cl], b21 = b2[ntile * 64 + cl + 1];
            float h0 = tanhf(accz[ms][ns][0] + b20);
            float h1v = tanhf(accz[ms][ns][1] + b21);
            float h2v = tanhf(accz[ms][ns][2] + b20);
            float h3 = tanhf(accz[ms][ns][3] + b21);
            dv[ms][0] = fmaf(acca[ms][ns][0], fmaf(h0, h0, -1.f), dv[ms][0]);
            dv[ms][0] = fmaf(acca[ms][ns][1], fmaf(h1v, h1v, -1.f), dv[ms][0]);
            dv[ms][1] = fmaf(acca[ms][ns][2], fmaf(h2v, h2v, -1.f), dv[ms][1]);
            dv[ms][1] = fmaf(acca[ms][ns][3], fmaf(h3, h3, -1.f), dv[ms][1]);
            float2 lo = make_float2(rtf32(h0), rtf32(h1v));
            float2 hi = make_float2(rtf32(h2v), rtf32(h3));
            *(float2*)&h2s[rl * 68 + cl]       = lo;
            *(float2*)&h2s[(rl + 8) * 68 + cl] = hi;
        }
#pragma unroll
    for (int ms = 0; ms < 4; ms++)
#pragma unroll
        for (int h = 0; h < 2; h++) {
            float v = dv[ms][h];
            v += __shfl_xor_sync(0xffffffffu, v, 1);
            v += __shfl_xor_sync(0xffffffffu, v, 2);
            if ((lane & 3) == 0) {
                int s = stile * 128 + warpm * 64 + ms * 16 + (lane >> 2) + h * 8;
                g_divp[(ntile * 2 + warpn) * B_ + s] = v;
            }
        }
    __syncthreads();

    // ---- partial out GEMM: po = h2s(128 x 64k) @ w3s(64k x 64m) ----
    float accp[4][4][4];
#pragma unroll
    for (int ms = 0; ms < 4; ms++)
#pragma unroll
        for (int ns = 0; ns < 4; ns++)
#pragma unroll
            for (int c = 0; c < 4; c++) accp[ms][ns][c] = 0.f;

#pragma unroll
    for (int ksp = 0; ksp < 8; ksp++) {
        uint32_t bf[4][2];
#pragma unroll
        for (int ns = 0; ns < 4; ns++) {
            int col = warpn * 32 + ns * 8 + (lane >> 2);
            int r0  = ksp * 8 + (lane & 3);
            bf[ns][0] = __float_as_uint(w3s[r0 * 68 + col]);
            bf[ns][1] = __float_as_uint(w3s[(r0 + 4) * 68 + col]);
        }
#pragma unroll
        for (int ms = 0; ms < 4; ms++) {
            int row = warpm * 64 + ms * 16 + (lane >> 2);
            int c0  = ksp * 8 + (lane & 3);
            uint32_t af[4];
            af[0] = __float_as_uint(h2s[row * 68 + c0]);
            af[1] = __float_as_uint(h2s[(row + 8) * 68 + c0]);
            af[2] = __float_as_uint(h2s[row * 68 + c0 + 4]);
            af[3] = __float_as_uint(h2s[(row + 8) * 68 + c0 + 4]);
#pragma unroll
            for (int ns = 0; ns < 4; ns++)
                mma_tf32(accp[ms][ns], af, bf[ns]);
        }
    }

    // store partials: g_outp[ntile][s][m], each element written exactly once
#pragma unroll
    for (int ms = 0; ms < 4; ms++)
#pragma unroll
        for (int ns = 0; ns < 4; ns++) {
            int rg = stile * 128 + warpm * 64 + ms * 16 + (lane >> 2);
            int cl = warpn * 32 + ns * 8 + 2 * (lane & 3);
            *(float2*)&g_outp[(size_t)(ntile * B_ + rg) * 64 + cl] =
                make_float2(accp[ms][ns][0], accp[ms][ns][1]);
            *(float2*)&g_outp[(size_t)(ntile * B_ + rg + 8) * 64 + cl] =
                make_float2(accp[ms][ns][2], accp[ms][ns][3]);
        }
}

// ---------------------------------------------------------------------------
// Kernel 4: reduce — out[s][m] = 0.5*(sum_nt outp[nt][s][m] + b3[m]);
//           out[s][64] = 0.5*sum_p divp[p][s].  128 blocks x 256 thr.
// ---------------------------------------------------------------------------
__global__ __launch_bounds__(256) void reduce_kernel(
    const float* __restrict__ b3, float* __restrict__ out)
{
    const int tid = threadIdx.x;
    const int m  = tid & 63;
    const int sl = tid >> 6;               // 0..3
    const int sb = blockIdx.x * 16;
    const float bm = b3[m];

#pragma unroll
    for (int i = 0; i < 4; i++) {
        int s = sb + sl * 4 + i;
        float acc = 0.f;
#pragma unroll
        for (int nt = 0; nt < 8; nt++)
            acc += g_outp[(size_t)(nt * B_ + s) * 64 + m];
        out[(size_t)s * 65 + m] = 0.5f * (acc + bm);
    }
    if (tid < 16) {
        int s = sb + tid;
        float d = 0.f;
#pragma unroll
        for (int p = 0; p < 16; p++) d += g_divp[p * B_ + s];
        out[(size_t)s * 65 + D_] = 0.5f * d;
    }
}

// ---------------------------------------------------------------------------
extern "C" void kernel_launch(void* const* d_in, const int* in_sizes, int n_in,
                              void* d_out, int out_size) {
    const float* t  = (const float*)d_in[0];
    const float* x  = (const float*)d_in[1];
    const float* W1 = (const float*)d_in[2];
    const float* b1 = (const float*)d_in[3];
    const float* W2 = (const float*)d_in[4];
    const float* b2 = (const float*)d_in[5];
    const float* W3 = (const float*)d_in[6];
    const float* b3 = (const float*)d_in[7];
    float* out = (float*)d_out;

    const int prep_smem = (512 * 65 + 8 * 64) * 4;
    const int gemm_smem = 2 * STG_F * 4;     // 110592 B
    cudaFuncSetAttribute(prep_kernel,  cudaFuncAttributeMaxDynamicSharedMemorySize, prep_smem);
    cudaFuncSetAttribute(gemm2_kernel, cudaFuncAttributeMaxDynamicSharedMemorySize, gemm_smem);

    prep_kernel<<<64, 512, prep_smem>>>(W1, W2, W3);
    phase1_kernel<<<B_ / 16, 512>>>(t, x, W1, b1);
    gemm2_kernel<<<dim3(B_ / 128, H_ / 64), 128, gemm_smem>>>(b2, W3);
    reduce_kernel<<<B_ / 16, 256>>>(b3, out);
}